// round 8
// baseline (speedup 1.0000x reference)
#include <cuda_runtime.h>
#include <cstdint>

#define Nn    100000
#define F     256
#define FS    32
#define FA    288
#define NLY   4
#define NG    50
#define NE_UP 400000
#define NE_L  300000
#define NE_TOT (NE_UP + 8 * NE_L)
#define SCAN_L (9 * Nn)
#define SCAN_BLK 1024
#define SCAN_NB ((SCAN_L + SCAN_BLK - 1) / SCAN_BLK)

// ---------------- device scratch ----------------
__device__ float g_x[(size_t)Nn * F];
__device__ float g_pi[(size_t)Nn * F];
__device__ float g_agg[(size_t)Nn * FA];
__device__ float g_agg16[(size_t)Nn * 16];
__device__ float g_dinv[(size_t)SCAN_L];
__device__ int   g_hist[(size_t)SCAN_L];
__device__ int   g_rp[(size_t)SCAN_L + 1];
__device__ int   g_col[(size_t)NE_TOT];
__device__ float g_we[(size_t)NE_TOT];
__device__ int   g_bsum[SCAN_NB];
__device__ int   g_boff[SCAN_NB];
__device__ int   g_total;
__device__ int   g_rows[(size_t)NLY * Nn];
__device__ int   g_cnt[NLY];
__device__ float g_WtIn[(size_t)256 * FA];
__device__ float g_WtFw[(size_t)256 * FA];
__device__ float g_WtUp[(size_t)256 * 16];

__device__ __forceinline__ uint32_t f2tf32(float f) {
    uint32_t r; asm("cvt.rna.tf32.f32 %0, %1;" : "=r"(r) : "f"(f)); return r;
}
__device__ __forceinline__ void mma_tf32(float* d, const uint32_t* a, const uint32_t* b) {
    asm volatile(
        "mma.sync.aligned.m16n8k8.row.col.f32.tf32.tf32.f32 "
        "{%0,%1,%2,%3}, {%4,%5,%6,%7}, {%8,%9}, {%0,%1,%2,%3};"
        : "+f"(d[0]), "+f"(d[1]), "+f"(d[2]), "+f"(d[3])
        : "r"(a[0]), "r"(a[1]), "r"(a[2]), "r"(a[3]), "r"(b[0]), "r"(b[1]));
}
__device__ __forceinline__ float4 fmaf4(float4 a, float w, float4 v) {
    a.x = fmaf(w, v.x, a.x); a.y = fmaf(w, v.y, a.y);
    a.z = fmaf(w, v.z, a.z); a.w = fmaf(w, v.w, a.w);
    return a;
}
__device__ __forceinline__ uint4 tf4(float4 v) {
    return make_uint4(f2tf32(v.x), f2tf32(v.y), f2tf32(v.z), f2tf32(v.w));
}

// ---------------- CSR build (deduped) ----------------
__global__ void k_hist0() {
    int i = blockIdx.x * blockDim.x + threadIdx.x;
    if (i < SCAN_L) g_hist[i] = 0;
    if (i < NLY) g_cnt[i] = 0;
}
__global__ void k_hist_multi(const int* __restrict__ base, int per, int nsets, int slot0) {
    int i = blockIdx.x * blockDim.x + threadIdx.x;
    if (i >= per * nsets) return;
    int set = i / per, e = i - set * per;
    int d = base[(size_t)set * 2 * per + per + e];
    atomicAdd(&g_hist[(size_t)(slot0 + set) * Nn + d], 1);
}
__global__ void k_scan1() {
    __shared__ int ws[8];
    int t = threadIdx.x;
    int base = blockIdx.x * SCAN_BLK + t * 4;
    int v[4], s = 0;
#pragma unroll
    for (int j = 0; j < 4; j++) {
        v[j] = (base + j < SCAN_L) ? g_hist[base + j] : 0;
        s += v[j];
    }
    int lane = t & 31, w = t >> 5;
    int inc = s;
#pragma unroll
    for (int o = 1; o < 32; o <<= 1) {
        int x = __shfl_up_sync(0xffffffffu, inc, o);
        if (lane >= o) inc += x;
    }
    if (lane == 31) ws[w] = inc;
    __syncthreads();
    if (t < 8) {
        int x = ws[t];
#pragma unroll
        for (int o = 1; o < 8; o <<= 1) {
            int y = __shfl_up_sync(0xffu, x, o);
            if (t >= o) x += y;
        }
        ws[t] = x;
    }
    __syncthreads();
    int run = inc - s + (w > 0 ? ws[w - 1] : 0);
#pragma unroll
    for (int j = 0; j < 4; j++) {
        if (base + j < SCAN_L) g_rp[base + j] = run;
        run += v[j];
    }
    __syncthreads();
    if (t == 255) g_bsum[blockIdx.x] = ws[7];
}
__global__ void k_scan2() {
    __shared__ int ws[32];
    int t = threadIdx.x;
    int v = (t < SCAN_NB) ? g_bsum[t] : 0;
    int lane = t & 31, w = t >> 5;
    int inc = v;
#pragma unroll
    for (int o = 1; o < 32; o <<= 1) {
        int x = __shfl_up_sync(0xffffffffu, inc, o);
        if (lane >= o) inc += x;
    }
    if (lane == 31) ws[w] = inc;
    __syncthreads();
    if (t < 32) {
        int x = ws[t];
#pragma unroll
        for (int o = 1; o < 32; o <<= 1) {
            int y = __shfl_up_sync(0xffffffffu, x, o);
            if (t >= o) x += y;
        }
        ws[t] = x;
    }
    __syncthreads();
    int excl = inc - v + (w > 0 ? ws[w - 1] : 0);
    if (t < SCAN_NB) g_boff[t] = excl;
    if (t == SCAN_NB - 1) g_total = excl + v;
}
__global__ void k_scan3() {     // + dinv + cursor fused
    int t = threadIdx.x;
    int off = g_boff[blockIdx.x];
    int base = blockIdx.x * SCAN_BLK + t * 4;
#pragma unroll
    for (int j = 0; j < 4; j++) {
        int i = base + j;
        if (i < SCAN_L) {
            int deg = g_hist[i];
            int rpv = g_rp[i] + off;
            g_rp[i] = rpv;
            g_dinv[i] = rsqrtf((float)(deg + 1));
            g_hist[i] = rpv;
        }
    }
    if (blockIdx.x == 0 && t == 0) g_rp[SCAN_L] = g_total;
}
__global__ void k_fill_multi(const int* __restrict__ base, int per, int nsets, int slot0) {
    int i = blockIdx.x * blockDim.x + threadIdx.x;
    if (i >= per * nsets) return;
    int set = i / per, e = i - set * per;
    const int* eb = base + (size_t)set * 2 * per;
    int s = eb[e], d = eb[per + e];
    int slot = slot0 + set;
    int pos = atomicAdd(&g_hist[(size_t)slot * Nn + d], 1);
    g_col[pos] = s;
    g_we[pos] = g_dinv[(size_t)slot * Nn + s];
}
__global__ void k_build(const int* __restrict__ layers) {
    int n = blockIdx.x * blockDim.x + threadIdx.x;
    if (n >= Nn) return;
    int il = layers[n];
    int p = atomicAdd(&g_cnt[il], 1);
    g_rows[(size_t)il * Nn + p] = n;
}
__global__ void k_transpose(const float* __restrict__ W, float* __restrict__ Wt, int K) {
    int i = blockIdx.x * blockDim.x + threadIdx.x;
    if (i >= K * 256) return;
    int k = i >> 8, n = i & 255;
    Wt[(size_t)n * K + k] = W[i];
}

// ---------------- up conv ----------------
__global__ void k_up_gather(const float* __restrict__ x16) {
    int i = blockIdx.x * blockDim.x + threadIdx.x;
    if (i >= Nn * 4) return;
    int n = i >> 2, q = i & 3;
    float dd = g_dinv[n];
    int r0 = g_rp[n], r1 = g_rp[n + 1];
    float4 a = ((const float4*)(x16 + (size_t)n * 16))[q];
    a.x *= dd; a.y *= dd; a.z *= dd; a.w *= dd;
    for (int e = r0; e < r1; e++) {
        int s = g_col[e];
        float wgt = g_we[e];
        a = fmaf4(a, wgt, ((const float4*)(x16 + (size_t)s * 16))[q]);
    }
    a.x *= dd; a.y *= dd; a.z *= dd; a.w *= dd;
    ((float4*)(g_agg16 + (size_t)n * 16))[q] = a;
}

#define ASTRIDE 36
__global__ void __launch_bounds__(256)
k_mma_gemm_up(const float* __restrict__ bias) {
    __shared__ uint32_t As[128 * ASTRIDE];
    __shared__ uint32_t Bs[128 * ASTRIDE];
    int row0 = blockIdx.y * 128;           // rows on y (col-pair adjacent in x)
    int colb = blockIdx.x * 128;
    int tid = threadIdx.x, wid = tid >> 5, lane = tid & 31;
    int wm = (wid >> 2) * 64, wn = (wid & 3) * 32;
    int q = lane >> 2, t = lane & 3;

    float acc[4][4][4];
#pragma unroll
    for (int i = 0; i < 4; i++)
#pragma unroll
        for (int j = 0; j < 4; j++)
#pragma unroll
            for (int k = 0; k < 4; k++) acc[i][j][k] = 0.f;
    {
        int idx = tid;
        for (int i = 0; i < 2; i++) {
            int e = idx + i * 256;
            int m = e >> 2, k4 = e & 3;
            int g = row0 + m;
            uint4 v = make_uint4(0, 0, 0, 0);
            if (g < Nn) v = tf4(*(const float4*)(g_agg16 + (size_t)g * 16 + k4 * 4));
            *(uint4*)(&As[m * ASTRIDE + k4 * 4]) = v;
        }
        for (int i = 0; i < 2; i++) {
            int e = idx + i * 256;
            int n = e >> 2, k4 = e & 3;
            float4 f = *(const float4*)(g_WtUp + (size_t)(colb + n) * 16 + k4 * 4);
            *(uint4*)(&Bs[n * ASTRIDE + k4 * 4]) = tf4(f);
        }
    }
    __syncthreads();
#pragma unroll
    for (int ks = 0; ks < 2; ks++) {
        int kc = ks * 8;
        uint32_t af[4][4];
#pragma unroll
        for (int mt = 0; mt < 4; mt++) {
            int r = wm + mt * 16 + q;
            af[mt][0] = As[r * ASTRIDE + kc + t];
            af[mt][1] = As[(r + 8) * ASTRIDE + kc + t];
            af[mt][2] = As[r * ASTRIDE + kc + t + 4];
            af[mt][3] = As[(r + 8) * ASTRIDE + kc + t + 4];
        }
        uint32_t bf[4][2];
#pragma unroll
        for (int nt = 0; nt < 4; nt++) {
            int n = wn + nt * 8 + q;
            bf[nt][0] = Bs[n * ASTRIDE + kc + t];
            bf[nt][1] = Bs[n * ASTRIDE + kc + t + 4];
        }
#pragma unroll
        for (int mt = 0; mt < 4; mt++)
#pragma unroll
            for (int nt = 0; nt < 4; nt++)
                mma_tf32(acc[mt][nt], af[mt], bf[nt]);
    }
#pragma unroll
    for (int mt = 0; mt < 4; mt++) {
        int n0 = row0 + wm + mt * 16 + q;
        int n1 = n0 + 8;
#pragma unroll
        for (int nt = 0; nt < 4; nt++) {
            int col = colb + wn + nt * 8 + t * 2;
            float b0 = bias[col], b1 = bias[col + 1];
            if (n0 < Nn)
                *(float2*)(g_x + (size_t)n0 * F + col) =
                    make_float2(acc[mt][nt][0] + b0, acc[mt][nt][1] + b1);
            if (n1 < Nn)
                *(float2*)(g_x + (size_t)n1 * F + col) =
                    make_float2(acc[mt][nt][2] + b0, acc[mt][nt][3] + b1);
        }
    }
}

// ---------------- aggregation: CSR gather (R4-proven) ----------------
__global__ void __launch_bounds__(256)
k_gather(const float* __restrict__ stat, int slot, int mask_il) {
    int w = threadIdx.x >> 5, lane = threadIdx.x & 31;
    int idx = blockIdx.x * 8 + w;
    int cnt = (mask_il >= 0) ? g_cnt[mask_il] : Nn;
    if (idx >= cnt) return;
    int n = (mask_il >= 0) ? g_rows[(size_t)mask_il * Nn + idx] : idx;
    size_t sb = (size_t)slot * Nn;
    float dd = g_dinv[sb + n];
    int e = g_rp[sb + n], e1 = g_rp[sb + n + 1];

    const float4* xn = (const float4*)(g_x + (size_t)n * F);
    float4 a0 = xn[lane], a1 = xn[lane + 32];
    float4 a2 = make_float4(0.f, 0.f, 0.f, 0.f);
    if (lane < 8) a2 = ((const float4*)(stat + (size_t)n * FS))[lane];
    a0.x *= dd; a0.y *= dd; a0.z *= dd; a0.w *= dd;
    a1.x *= dd; a1.y *= dd; a1.z *= dd; a1.w *= dd;
    a2.x *= dd; a2.y *= dd; a2.z *= dd; a2.w *= dd;
    int sn = 0; float wn_ = 0.f;
    if (e < e1) { sn = g_col[e]; wn_ = g_we[e]; }
    while (e < e1) {
        int s = sn; float wgt = wn_;
        if (e + 1 < e1) { sn = g_col[e + 1]; wn_ = g_we[e + 1]; }
        const float4* xs = (const float4*)(g_x + (size_t)s * F);
        a0 = fmaf4(a0, wgt, xs[lane]);
        a1 = fmaf4(a1, wgt, xs[lane + 32]);
        if (lane < 8)
            a2 = fmaf4(a2, wgt, ((const float4*)(stat + (size_t)s * FS))[lane]);
        e++;
    }
    a0.x *= dd; a0.y *= dd; a0.z *= dd; a0.w *= dd;
    a1.x *= dd; a1.y *= dd; a1.z *= dd; a1.w *= dd;
    a2.x *= dd; a2.y *= dd; a2.z *= dd; a2.w *= dd;

    float4* ag = (float4*)(g_agg + (size_t)n * FA);
    ag[lane] = a0;
    ag[lane + 32] = a1;
    if (lane < 8) ag[lane + 64] = a2;
}

// ---------------- R4-proven GEMM: 256 thr, M=128 x N=128, rows on blockIdx.y ----------------
__global__ void __launch_bounds__(256)
k_mma_gemm(const float* __restrict__ Wt, const float* __restrict__ bias,
           int mask_il, int to_pi) {
    __shared__ uint32_t As[128 * ASTRIDE];
    __shared__ uint32_t Bs[128 * ASTRIDE];

    int cnt = (mask_il >= 0) ? g_cnt[mask_il] : Nn;
    const int* list = (mask_il >= 0) ? (g_rows + (size_t)mask_il * Nn) : nullptr;
    int row0 = blockIdx.y * 128;          // rows on y
    if (row0 >= cnt) return;
    int colb = blockIdx.x * 128;          // col-pair adjacent in issue order

    int tid = threadIdx.x, wid = tid >> 5, lane = tid & 31;
    int wm = (wid >> 2) * 64;
    int wn = (wid & 3) * 32;
    int q = lane >> 2, t = lane & 3;

    float acc[4][4][4];
#pragma unroll
    for (int i = 0; i < 4; i++)
#pragma unroll
        for (int j = 0; j < 4; j++)
#pragma unroll
            for (int k = 0; k < 4; k++) acc[i][j][k] = 0.f;

    int amrow[4];
#pragma unroll
    for (int i = 0; i < 4; i++) {
        int m = (tid + i * 256) >> 3;
        int g = row0 + m;
        amrow[i] = (g < cnt) ? (list ? list[g] : g) : (list ? list[row0] : row0);
    }

    for (int kt = 0; kt < FA; kt += 32) {
#pragma unroll
        for (int i = 0; i < 4; i++) {
            int idx = tid + i * 256;
            int m = idx >> 3, k4 = idx & 7;
            float4 f = *(const float4*)(g_agg + (size_t)amrow[i] * FA + kt + k4 * 4);
            *(uint4*)(&As[m * ASTRIDE + k4 * 4]) = tf4(f);
        }
#pragma unroll
        for (int i = 0; i < 4; i++) {
            int idx = tid + i * 256;
            int n = idx >> 3, k4 = idx & 7;
            float4 f = *(const float4*)(Wt + (size_t)(colb + n) * FA + kt + k4 * 4);
            *(uint4*)(&Bs[n * ASTRIDE + k4 * 4]) = tf4(f);
        }
        __syncthreads();
#pragma unroll
        for (int ks = 0; ks < 4; ks++) {
            int kc = ks * 8;
            uint32_t af[4][4];
#pragma unroll
            for (int mt = 0; mt < 4; mt++) {
                int r = wm + mt * 16 + q;
                af[mt][0] = As[r * ASTRIDE + kc + t];
                af[mt][1] = As[(r + 8) * ASTRIDE + kc + t];
                af[mt][2] = As[r * ASTRIDE + kc + t + 4];
                af[mt][3] = As[(r + 8) * ASTRIDE + kc + t + 4];
            }
            uint32_t bf[4][2];
#pragma unroll
            for (int nt = 0; nt < 4; nt++) {
                int n = wn + nt * 8 + q;
                bf[nt][0] = Bs[n * ASTRIDE + kc + t];
                bf[nt][1] = Bs[n * ASTRIDE + kc + t + 4];
            }
#pragma unroll
            for (int mt = 0; mt < 4; mt++)
#pragma unroll
                for (int nt = 0; nt < 4; nt++)
                    mma_tf32(acc[mt][nt], af[mt], bf[nt]);
        }
        __syncthreads();
    }

    float* outb = to_pi ? g_pi : g_x;
#pragma unroll
    for (int mt = 0; mt < 4; mt++) {
        int g0 = row0 + wm + mt * 16 + q;
        int g1 = g0 + 8;
        int n0 = (g0 < cnt) ? (list ? list[g0] : g0) : -1;
        int n1 = (g1 < cnt) ? (list ? list[g1] : g1) : -1;
#pragma unroll
        for (int nt = 0; nt < 4; nt++) {
            int col = colb + wn + nt * 8 + t * 2;
            float b0 = bias[col], b1 = bias[col + 1];
            if (n0 >= 0)
                *(float2*)(outb + (size_t)n0 * F + col) =
                    make_float2(acc[mt][nt][0] + b0, acc[mt][nt][1] + b1);
            if (n1 >= 0)
                *(float2*)(outb + (size_t)n1 * F + col) =
                    make_float2(acc[mt][nt][2] + b0, acc[mt][nt][3] + b1);
        }
    }
}

// ---------------- misc ----------------
__global__ void k_copy_rows(int il) {
    int c = threadIdx.x % 64, r = threadIdx.x / 64;
    int idx = blockIdx.x * 4 + r;
    if (idx >= g_cnt[il]) return;
    int n = g_rows[(size_t)il * Nn + idx];
    ((float4*)(g_x + (size_t)n * F))[c] = ((const float4*)(g_pi + (size_t)n * F))[c];
}
__global__ void k_relu_copy3(const int* __restrict__ layers) {   // x = relu(layers==3 ? pi : x)
    int i = blockIdx.x * blockDim.x + threadIdx.x;
    if (i >= Nn * 64) return;
    int n = i >> 6;
    float4 v = (layers[n] == 3) ? ((const float4*)g_pi)[i] : ((const float4*)g_x)[i];
    v.x = fmaxf(v.x, 0.f); v.y = fmaxf(v.y, 0.f);
    v.z = fmaxf(v.z, 0.f); v.w = fmaxf(v.w, 0.f);
    ((float4*)g_x)[i] = v;
}
__global__ void k_relu4() {
    int i = blockIdx.x * blockDim.x + threadIdx.x;
    if (i >= Nn * F / 4) return;
    float4* p = (float4*)g_x;
    float4 v = p[i];
    v.x = fmaxf(v.x, 0.f); v.y = fmaxf(v.y, 0.f);
    v.z = fmaxf(v.z, 0.f); v.w = fmaxf(v.w, 0.f);
    p[i] = v;
}
__global__ void k_pool_init(const float* __restrict__ bl, float* __restrict__ out) {
    int g = threadIdx.x;
    if (g < NG) out[g] = bl[0];
}
__global__ void k_pool(const int* __restrict__ batch, const float* __restrict__ Wl,
                       float* __restrict__ out) {
    int w = (blockIdx.x * blockDim.x + threadIdx.x) >> 5;
    int lane = threadIdx.x & 31;
    if (w >= Nn) return;
    const float* xr = g_x + (size_t)w * F;
    float s = 0.f;
    for (int c = lane; c < F; c += 32) s += xr[c] * Wl[c];
#pragma unroll
    for (int o = 16; o; o >>= 1) s += __shfl_down_sync(0xffffffffu, s, o);
    if (lane == 0) atomicAdd(&out[batch[w]], s);
}

// ---------------- orchestration ----------------
extern "C" void kernel_launch(void* const* d_in, const int* in_sizes, int n_in,
                              void* d_out, int out_size) {
    const float* x16    = (const float*)d_in[0];
    const float* stat   = (const float*)d_in[1];
    const int*   eidx   = (const int*)d_in[2];
    const int*   einner = (const int*)d_in[3];
    const int*   efw    = (const int*)d_in[4];
    const int*   layers = (const int*)d_in[6];
    const int*   batch  = (const int*)d_in[7];
    const float* W_up  = (const float*)d_in[8];
    const float* b_up  = (const float*)d_in[9];
    const float* W_in  = (const float*)d_in[10];
    const float* b_in  = (const float*)d_in[11];
    const float* W_fw  = (const float*)d_in[12];
    const float* b_fw  = (const float*)d_in[13];
    const float* W_lin = (const float*)d_in[14];
    const float* b_lin = (const float*)d_in[15];
    float* out = (float*)d_out;

    float* d_WtIn; cudaGetSymbolAddress((void**)&d_WtIn, g_WtIn);
    float* d_WtFw; cudaGetSymbolAddress((void**)&d_WtFw, g_WtFw);
    float* d_WtUp; cudaGetSymbolAddress((void**)&d_WtUp, g_WtUp);

    // ---- CSR build ----
    k_hist0<<<(SCAN_L + 255) / 256, 256>>>();
    k_hist_multi<<<(NE_UP + 255) / 256, 256>>>(eidx, NE_UP, 1, 0);
    k_hist_multi<<<(4 * NE_L + 255) / 256, 256>>>(einner, NE_L, 4, 1);
    k_hist_multi<<<(4 * NE_L + 255) / 256, 256>>>(efw, NE_L, 4, 5);
    k_scan1<<<SCAN_NB, 256>>>();
    k_scan2<<<1, 1024>>>();
    k_scan3<<<SCAN_NB, 256>>>();
    k_fill_multi<<<(NE_UP + 255) / 256, 256>>>(eidx, NE_UP, 1, 0);
    k_fill_multi<<<(4 * NE_L + 255) / 256, 256>>>(einner, NE_L, 4, 1);
    k_fill_multi<<<(4 * NE_L + 255) / 256, 256>>>(efw, NE_L, 4, 5);
    k_build<<<(Nn + 255) / 256, 256>>>(layers);
    k_transpose<<<(FA * 256 + 255) / 256, 256>>>(W_in, d_WtIn, FA);
    k_transpose<<<(FA * 256 + 255) / 256, 256>>>(W_fw, d_WtFw, FA);
    k_transpose<<<(16 * 256 + 255) / 256, 256>>>(W_up, d_WtUp, 16);

    const int GX  = (Nn + 127) / 128;
    const int GC  = (Nn + 3) / 4;
    const int GG  = (Nn + 7) / 8;

    // ---- up conv ----
    k_up_gather<<<(Nn * 4 + 255) / 256, 256>>>(x16);
    k_mma_gemm_up<<<dim3(2, GX), 256>>>(b_up);

    auto conv = [&](int slot, int mask, const float* Wt, const float* bb, int to_pi) {
        k_gather<<<GG, 256>>>(stat, slot, mask);
        k_mma_gemm<<<dim3(2, GX), 256>>>(Wt, bb, mask, to_pi);
    };

    for (int p = 0; p < 2; p++) {
        for (int il = 0; il < 3; il++) {
            conv(1 + il, il, d_WtIn, b_in, 0);          // inner -> rows(il)
            conv(5 + il, il + 1, d_WtFw, b_fw, 0);      // fw    -> rows(il+1)
        }
        conv(4, -1, d_WtIn, b_in, 1);                   // full -> pi
        k_relu_copy3<<<(Nn * 64 + 255) / 256, 256>>>(layers);
        for (int il = 3; il >= 0; il--) {
            if (il >= 1) k_copy_rows<<<GC, 256>>>(il - 1);
            conv(1 + il, il, d_WtIn, b_in, 0);
        }
        k_relu4<<<(Nn * F / 4 + 255) / 256, 256>>>();
    }

    k_pool_init<<<1, 64>>>(b_lin, out);
    k_pool<<<(Nn * 32 + 255) / 256, 256>>>(batch, W_lin, out);
}

// round 11
// speedup vs baseline: 1.3596x; 1.3596x over previous
#include <cuda_runtime.h>
#include <cuda_fp16.h>
#include <cstdint>

#define Nn    100000
#define F     256
#define FS    32
#define FA    288
#define NLY   4
#define NG    50
#define NE_UP 400000
#define NE_L  300000
#define NE_TOT (NE_UP + 8 * NE_L)
#define SCAN_L (9 * Nn)
#define SCAN_BLK 1024
#define SCAN_NB ((SCAN_L + SCAN_BLK - 1) / SCAN_BLK)

// ---------------- device scratch ----------------
__device__ float g_x[(size_t)Nn * F];                 // fp32 state
__device__ float g_pi[(size_t)Nn * F];                // fp32 state
__device__ __half g_agg[(size_t)Nn * FA];             // fp16 GEMM A
__device__ float g_agg16[(size_t)Nn * 16];
__device__ float g_dinv[(size_t)SCAN_L];
__device__ int   g_hist[(size_t)SCAN_L];
__device__ int   g_rp[(size_t)SCAN_L + 1];
__device__ int   g_col[(size_t)NE_TOT];
__device__ float g_we[(size_t)NE_TOT];
__device__ int   g_bsum[SCAN_NB];
__device__ int   g_boff[SCAN_NB];
__device__ int   g_total;
__device__ int   g_rows[(size_t)NLY * Nn];
__device__ int   g_cnt[NLY];
__device__ __half g_WtIn[(size_t)256 * FA];           // fp16 W^T
__device__ __half g_WtFw[(size_t)256 * FA];
__device__ float g_WtUp[(size_t)256 * 16];

__device__ __forceinline__ uint32_t f2tf32(float f) {
    uint32_t r; asm("cvt.rna.tf32.f32 %0, %1;" : "=r"(r) : "f"(f)); return r;
}
__device__ __forceinline__ uint4 tf4(float4 v) {
    return make_uint4(f2tf32(v.x), f2tf32(v.y), f2tf32(v.z), f2tf32(v.w));
}
__device__ __forceinline__ void mma_tf32(float* d, const uint32_t* a, const uint32_t* b) {
    asm volatile(
        "mma.sync.aligned.m16n8k8.row.col.f32.tf32.tf32.f32 "
        "{%0,%1,%2,%3}, {%4,%5,%6,%7}, {%8,%9}, {%0,%1,%2,%3};"
        : "+f"(d[0]), "+f"(d[1]), "+f"(d[2]), "+f"(d[3])
        : "r"(a[0]), "r"(a[1]), "r"(a[2]), "r"(a[3]), "r"(b[0]), "r"(b[1]));
}
__device__ __forceinline__ void mma_f16(float* d, const uint32_t* a, const uint32_t* b) {
    asm volatile(
        "mma.sync.aligned.m16n8k16.row.col.f32.f16.f16.f32 "
        "{%0,%1,%2,%3}, {%4,%5,%6,%7}, {%8,%9}, {%0,%1,%2,%3};"
        : "+f"(d[0]), "+f"(d[1]), "+f"(d[2]), "+f"(d[3])
        : "r"(a[0]), "r"(a[1]), "r"(a[2]), "r"(a[3]), "r"(b[0]), "r"(b[1]));
}
__device__ __forceinline__ float4 fmaf4(float4 a, float w, float4 v) {
    a.x = fmaf(w, v.x, a.x); a.y = fmaf(w, v.y, a.y);
    a.z = fmaf(w, v.z, a.z); a.w = fmaf(w, v.w, a.w);
    return a;
}
__device__ __forceinline__ uint2 packf4(float4 v) {
    __half2 h0 = __floats2half2_rn(v.x, v.y);
    __half2 h1 = __floats2half2_rn(v.z, v.w);
    return make_uint2(*(uint32_t*)&h0, *(uint32_t*)&h1);
}

// ---------------- CSR build (R4-identical) ----------------
__global__ void k_hist0() {
    int i = blockIdx.x * blockDim.x + threadIdx.x;
    if (i < SCAN_L) g_hist[i] = 0;
    if (i < NLY) g_cnt[i] = 0;
}
__global__ void k_hist(const int* __restrict__ dst, int nE, int slot) {
    int i = blockIdx.x * blockDim.x + threadIdx.x;
    if (i >= nE) return;
    atomicAdd(&g_hist[(size_t)slot * Nn + dst[i]], 1);
}
__global__ void k_scan1() {
    __shared__ int ws[8];
    int t = threadIdx.x;
    int base = blockIdx.x * SCAN_BLK + t * 4;
    int v[4], s = 0;
#pragma unroll
    for (int j = 0; j < 4; j++) {
        v[j] = (base + j < SCAN_L) ? g_hist[base + j] : 0;
        s += v[j];
    }
    int lane = t & 31, w = t >> 5;
    int inc = s;
#pragma unroll
    for (int o = 1; o < 32; o <<= 1) {
        int x = __shfl_up_sync(0xffffffffu, inc, o);
        if (lane >= o) inc += x;
    }
    if (lane == 31) ws[w] = inc;
    __syncthreads();
    if (t < 8) {
        int x = ws[t];
#pragma unroll
        for (int o = 1; o < 8; o <<= 1) {
            int y = __shfl_up_sync(0xffu, x, o);
            if (t >= o) x += y;
        }
        ws[t] = x;
    }
    __syncthreads();
    int run = inc - s + (w > 0 ? ws[w - 1] : 0);
#pragma unroll
    for (int j = 0; j < 4; j++) {
        if (base + j < SCAN_L) g_rp[base + j] = run;
        run += v[j];
    }
    __syncthreads();
    if (t == 255) g_bsum[blockIdx.x] = ws[7];
}
__global__ void k_scan2() {
    __shared__ int ws[32];
    int t = threadIdx.x;
    int v = (t < SCAN_NB) ? g_bsum[t] : 0;
    int lane = t & 31, w = t >> 5;
    int inc = v;
#pragma unroll
    for (int o = 1; o < 32; o <<= 1) {
        int x = __shfl_up_sync(0xffffffffu, inc, o);
        if (lane >= o) inc += x;
    }
    if (lane == 31) ws[w] = inc;
    __syncthreads();
    if (t < 32) {
        int x = ws[t];
#pragma unroll
        for (int o = 1; o < 32; o <<= 1) {
            int y = __shfl_up_sync(0xffffffffu, x, o);
            if (t >= o) x += y;
        }
        ws[t] = x;
    }
    __syncthreads();
    int excl = inc - v + (w > 0 ? ws[w - 1] : 0);
    if (t < SCAN_NB) g_boff[t] = excl;
    if (t == SCAN_NB - 1) g_total = excl + v;
}
__global__ void k_scan3() {
    int t = threadIdx.x;
    int off = g_boff[blockIdx.x];
    int base = blockIdx.x * SCAN_BLK + t * 4;
#pragma unroll
    for (int j = 0; j < 4; j++)
        if (base + j < SCAN_L) g_rp[base + j] += off;
    if (blockIdx.x == 0 && t == 0) g_rp[SCAN_L] = g_total;
}
__global__ void k_dinv() {
    int i = blockIdx.x * blockDim.x + threadIdx.x;
    if (i < SCAN_L) g_dinv[i] = rsqrtf((float)(g_hist[i] + 1));
}
__global__ void k_cursor() {
    int i = blockIdx.x * blockDim.x + threadIdx.x;
    if (i < SCAN_L) g_hist[i] = g_rp[i];
}
__global__ void k_fill(const int* __restrict__ src, const int* __restrict__ dst,
                       int nE, int slot) {
    int e = blockIdx.x * blockDim.x + threadIdx.x;
    if (e >= nE) return;
    int d = dst[e], s = src[e];
    int pos = atomicAdd(&g_hist[(size_t)slot * Nn + d], 1);
    g_col[pos] = s;
    g_we[pos] = g_dinv[(size_t)slot * Nn + s];
}
__global__ void k_build(const int* __restrict__ layers) {
    int n = blockIdx.x * blockDim.x + threadIdx.x;
    if (n >= Nn) return;
    int il = layers[n];
    int p = atomicAdd(&g_cnt[il], 1);
    g_rows[(size_t)il * Nn + p] = n;
}
__global__ void k_transpose_h(const float* __restrict__ W, __half* __restrict__ Wt, int K) {
    int i = blockIdx.x * blockDim.x + threadIdx.x;
    if (i >= K * 256) return;
    int k = i >> 8, n = i & 255;
    Wt[(size_t)n * K + k] = __float2half_rn(W[i]);
}
__global__ void k_transpose(const float* __restrict__ W, float* __restrict__ Wt, int K) {
    int i = blockIdx.x * blockDim.x + threadIdx.x;
    if (i >= K * 256) return;
    int k = i >> 8, n = i & 255;
    Wt[(size_t)n * K + k] = W[i];
}

// ---------------- up conv (R4-identical, fp32/tf32) ----------------
__global__ void k_up_gather(const float* __restrict__ x16) {
    int i = blockIdx.x * blockDim.x + threadIdx.x;
    if (i >= Nn * 4) return;
    int n = i >> 2, q = i & 3;
    float dd = g_dinv[n];
    int r0 = g_rp[n], r1 = g_rp[n + 1];
    float4 a = ((const float4*)(x16 + (size_t)n * 16))[q];
    a.x *= dd; a.y *= dd; a.z *= dd; a.w *= dd;
    for (int e = r0; e < r1; e++) {
        int s = g_col[e];
        float wgt = g_we[e];
        a = fmaf4(a, wgt, ((const float4*)(x16 + (size_t)s * 16))[q]);
    }
    a.x *= dd; a.y *= dd; a.z *= dd; a.w *= dd;
    ((float4*)(g_agg16 + (size_t)n * 16))[q] = a;
}

#define ASTRIDE 36
__global__ void __launch_bounds__(256)
k_mma_gemm_up(const float* __restrict__ bias) {
    __shared__ uint32_t As[128 * ASTRIDE];
    __shared__ uint32_t Bs[128 * ASTRIDE];
    int row0 = blockIdx.x * 128;
    int colb = blockIdx.y * 128;
    int tid = threadIdx.x, wid = tid >> 5, lane = tid & 31;
    int wm = (wid >> 2) * 64, wn = (wid & 3) * 32;
    int q = lane >> 2, t = lane & 3;

    float acc[4][4][4];
#pragma unroll
    for (int i = 0; i < 4; i++)
#pragma unroll
        for (int j = 0; j < 4; j++)
#pragma unroll
            for (int k = 0; k < 4; k++) acc[i][j][k] = 0.f;
    {
        int idx = tid;
        for (int i = 0; i < 2; i++) {
            int e = idx + i * 256;
            int m = e >> 2, k4 = e & 3;
            int g = row0 + m;
            uint4 v = make_uint4(0, 0, 0, 0);
            if (g < Nn) v = tf4(*(const float4*)(g_agg16 + (size_t)g * 16 + k4 * 4));
            *(uint4*)(&As[m * ASTRIDE + k4 * 4]) = v;
        }
        for (int i = 0; i < 2; i++) {
            int e = idx + i * 256;
            int n = e >> 2, k4 = e & 3;
            float4 f = *(const float4*)(g_WtUp + (size_t)(colb + n) * 16 + k4 * 4);
            *(uint4*)(&Bs[n * ASTRIDE + k4 * 4]) = tf4(f);
        }
    }
    __syncthreads();
#pragma unroll
    for (int ks = 0; ks < 2; ks++) {
        int kc = ks * 8;
        uint32_t af[4][4];
#pragma unroll
        for (int mt = 0; mt < 4; mt++) {
            int r = wm + mt * 16 + q;
            af[mt][0] = As[r * ASTRIDE + kc + t];
            af[mt][1] = As[(r + 8) * ASTRIDE + kc + t];
            af[mt][2] = As[r * ASTRIDE + kc + t + 4];
            af[mt][3] = As[(r + 8) * ASTRIDE + kc + t + 4];
        }
        uint32_t bf[4][2];
#pragma unroll
        for (int nt = 0; nt < 4; nt++) {
            int n = wn + nt * 8 + q;
            bf[nt][0] = Bs[n * ASTRIDE + kc + t];
            bf[nt][1] = Bs[n * ASTRIDE + kc + t + 4];
        }
#pragma unroll
        for (int mt = 0; mt < 4; mt++)
#pragma unroll
            for (int nt = 0; nt < 4; nt++)
                mma_tf32(acc[mt][nt], af[mt], bf[nt]);
    }
#pragma unroll
    for (int mt = 0; mt < 4; mt++) {
        int n0 = row0 + wm + mt * 16 + q;
        int n1 = n0 + 8;
#pragma unroll
        for (int nt = 0; nt < 4; nt++) {
            int col = colb + wn + nt * 8 + t * 2;
            float b0 = bias[col], b1 = bias[col + 1];
            if (n0 < Nn)
                *(float2*)(g_x + (size_t)n0 * F + col) =
                    make_float2(acc[mt][nt][0] + b0, acc[mt][nt][1] + b1);
            if (n1 < Nn)
                *(float2*)(g_x + (size_t)n1 * F + col) =
                    make_float2(acc[mt][nt][2] + b0, acc[mt][nt][3] + b1);
        }
    }
}

// ---------------- gather: fp32 x -> fp16 agg (R4 gather + pack) ----------------
__global__ void __launch_bounds__(256)
k_gather(const float* __restrict__ stat, int slot, int mask_il) {
    int w = threadIdx.x >> 5, lane = threadIdx.x & 31;
    int idx = blockIdx.x * 8 + w;
    int cnt = (mask_il >= 0) ? g_cnt[mask_il] : Nn;
    if (idx >= cnt) return;
    int n = (mask_il >= 0) ? g_rows[(size_t)mask_il * Nn + idx] : idx;
    size_t sb = (size_t)slot * Nn;
    float dd = g_dinv[sb + n];
    int e = g_rp[sb + n], e1 = g_rp[sb + n + 1];

    const float4* xn = (const float4*)(g_x + (size_t)n * F);
    float4 a0 = xn[lane], a1 = xn[lane + 32];
    float4 a2 = make_float4(0.f, 0.f, 0.f, 0.f);
    if (lane < 8) a2 = ((const float4*)(stat + (size_t)n * FS))[lane];
    a0.x *= dd; a0.y *= dd; a0.z *= dd; a0.w *= dd;
    a1.x *= dd; a1.y *= dd; a1.z *= dd; a1.w *= dd;
    a2.x *= dd; a2.y *= dd; a2.z *= dd; a2.w *= dd;
    int sn = 0; float wn_ = 0.f;
    if (e < e1) { sn = g_col[e]; wn_ = g_we[e]; }
    while (e < e1) {
        int s = sn; float wgt = wn_;
        if (e + 1 < e1) { sn = g_col[e + 1]; wn_ = g_we[e + 1]; }
        const float4* xs = (const float4*)(g_x + (size_t)s * F);
        a0 = fmaf4(a0, wgt, xs[lane]);
        a1 = fmaf4(a1, wgt, xs[lane + 32]);
        if (lane < 8)
            a2 = fmaf4(a2, wgt, ((const float4*)(stat + (size_t)s * FS))[lane]);
        e++;
    }
    a0.x *= dd; a0.y *= dd; a0.z *= dd; a0.w *= dd;
    a1.x *= dd; a1.y *= dd; a1.z *= dd; a1.w *= dd;
    a2.x *= dd; a2.y *= dd; a2.z *= dd; a2.w *= dd;

    uint2* ag = (uint2*)(g_agg + (size_t)n * FA);   // 144 uint2 per row
    ag[lane] = packf4(a0);
    ag[lane + 32] = packf4(a1);
    if (lane < 8) ag[lane + 64] = packf4(a2);
}

// ---------------- fp16 GEMM: 256 thr, M=128 x N=128, m16n8k16, fp32 out ----------------
#define BST 20
__global__ void __launch_bounds__(256)
k_mma_gemm(const __half* __restrict__ Wt, const float* __restrict__ bias,
           int mask_il, int to_pi) {
    __shared__ uint32_t As[128 * BST];
    __shared__ uint32_t Bs[128 * BST];

    int cnt = (mask_il >= 0) ? g_cnt[mask_il] : Nn;
    const int* list = (mask_il >= 0) ? (g_rows + (size_t)mask_il * Nn) : nullptr;
    int row0 = blockIdx.x * 128;
    if (row0 >= cnt) return;
    int colb = blockIdx.y * 128;

    int tid = threadIdx.x, wid = tid >> 5, lane = tid & 31;
    int wm = (wid >> 2) * 64;
    int wn = (wid & 3) * 32;
    int q = lane >> 2, t = lane & 3;

    float acc[4][4][4];
#pragma unroll
    for (int i = 0; i < 4; i++)
#pragma unroll
        for (int j = 0; j < 4; j++)
#pragma unroll
            for (int k = 0; k < 4; k++) acc[i][j][k] = 0.f;

    int amrow[2];
#pragma unroll
    for (int i = 0; i < 2; i++) {
        int m = (tid + i * 256) >> 2;
        int g = row0 + m;
        amrow[i] = (g < cnt) ? (list ? list[g] : g) : (list ? list[row0] : row0);
    }

    for (int kt = 0; kt < FA; kt += 32) {      // 9 chunks; 16 u32 (32 fp16) per row
#pragma unroll
        for (int i = 0; i < 2; i++) {
            int idx = tid + i * 256;
            int m = idx >> 2, k4 = idx & 3;
            uint4 v = *(const uint4*)((const uint32_t*)(g_agg + (size_t)amrow[i] * FA)
                                      + (kt >> 1) + k4 * 4);
            *(uint4*)(&As[m * BST + k4 * 4]) = v;
        }
#pragma unroll
        for (int i = 0; i < 2; i++) {
            int idx = tid + i * 256;
            int n = idx >> 2, k4 = idx & 3;
            uint4 v = *(const uint4*)((const uint32_t*)(Wt + (size_t)(colb + n) * FA)
                                      + (kt >> 1) + k4 * 4);
            *(uint4*)(&Bs[n * BST + k4 * 4]) = v;
        }
        __syncthreads();
#pragma unroll
        for (int ks = 0; ks < 2; ks++) {
            int kc = ks * 8;
            uint32_t af[4][4];
#pragma unroll
            for (int mt = 0; mt < 4; mt++) {
                int r = wm + mt * 16 + q;
                af[mt][0] = As[r * BST + kc + t];
                af[mt][1] = As[(r + 8) * BST + kc + t];
                af[mt][2] = As[r * BST + kc + t + 4];
                af[mt][3] = As[(r + 8) * BST + kc + t + 4];
            }
            uint32_t bf[4][2];
#pragma unroll
            for (int nt = 0; nt < 4; nt++) {
                int n = wn + nt * 8 + q;
                bf[nt][0] = Bs[n * BST + kc + t];
                bf[nt][1] = Bs[n * BST + kc + t + 4];
            }
#pragma unroll
            for (int mt = 0; mt < 4; mt++)
#pragma unroll
                for (int nt = 0; nt < 4; nt++)
                    mma_f16(acc[mt][nt], af[mt], bf[nt]);
        }
        __syncthreads();
    }

    float* outb = to_pi ? g_pi : g_x;
#pragma unroll
    for (int mt = 0; mt < 4; mt++) {
        int g0 = row0 + wm + mt * 16 + q;
        int g1 = g0 + 8;
        int n0 = (g0 < cnt) ? (list ? list[g0] : g0) : -1;
        int n1 = (g1 < cnt) ? (list ? list[g1] : g1) : -1;
#pragma unroll
        for (int nt = 0; nt < 4; nt++) {
            int col = colb + wn + nt * 8 + t * 2;
            float b0 = bias[col], b1 = bias[col + 1];
            if (n0 >= 0)
                *(float2*)(outb + (size_t)n0 * F + col) =
                    make_float2(acc[mt][nt][0] + b0, acc[mt][nt][1] + b1);
            if (n1 >= 0)
                *(float2*)(outb + (size_t)n1 * F + col) =
                    make_float2(acc[mt][nt][2] + b0, acc[mt][nt][3] + b1);
        }
    }
}

// ---------------- misc (R4-identical, fp32) ----------------
__global__ void k_copy_rows(int il) {
    int c = threadIdx.x % 64, r = threadIdx.x / 64;
    int idx = blockIdx.x * 4 + r;
    if (idx >= g_cnt[il]) return;
    int n = g_rows[(size_t)il * Nn + idx];
    ((float4*)(g_x + (size_t)n * F))[c] = ((const float4*)(g_pi + (size_t)n * F))[c];
}
__global__ void k_relu4() {
    int i = blockIdx.x * blockDim.x + threadIdx.x;
    if (i >= Nn * F / 4) return;
    float4* p = (float4*)g_x;
    float4 v = p[i];
    v.x = fmaxf(v.x, 0.f); v.y = fmaxf(v.y, 0.f);
    v.z = fmaxf(v.z, 0.f); v.w = fmaxf(v.w, 0.f);
    p[i] = v;
}
__global__ void k_pool_init(const float* __restrict__ bl, float* __restrict__ out) {
    int g = threadIdx.x;
    if (g < NG) out[g] = bl[0];
}
__global__ void k_pool(const int* __restrict__ batch, const float* __restrict__ Wl,
                       float* __restrict__ out) {
    int w = (blockIdx.x * blockDim.x + threadIdx.x) >> 5;
    int lane = threadIdx.x & 31;
    if (w >= Nn) return;
    const float* xr = g_x + (size_t)w * F;
    float s = 0.f;
    for (int c = lane; c < F; c += 32) s += xr[c] * Wl[c];
#pragma unroll
    for (int o = 16; o; o >>= 1) s += __shfl_down_sync(0xffffffffu, s, o);
    if (lane == 0) atomicAdd(&out[batch[w]], s);
}

// ---------------- orchestration (R4-identical sequence) ----------------
extern "C" void kernel_launch(void* const* d_in, const int* in_sizes, int n_in,
                              void* d_out, int out_size) {
    const float* x16    = (const float*)d_in[0];
    const float* stat   = (const float*)d_in[1];
    const int*   eidx   = (const int*)d_in[2];
    const int*   einner = (const int*)d_in[3];
    const int*   efw    = (const int*)d_in[4];
    const int*   layers = (const int*)d_in[6];
    const int*   batch  = (const int*)d_in[7];
    const float* W_up  = (const float*)d_in[8];
    const float* b_up  = (const float*)d_in[9];
    const float* W_in  = (const float*)d_in[10];
    const float* b_in  = (const float*)d_in[11];
    const float* W_fw  = (const float*)d_in[12];
    const float* b_fw  = (const float*)d_in[13];
    const float* W_lin = (const float*)d_in[14];
    const float* b_lin = (const float*)d_in[15];
    float* out = (float*)d_out;

    __half* d_WtIn; cudaGetSymbolAddress((void**)&d_WtIn, g_WtIn);
    __half* d_WtFw; cudaGetSymbolAddress((void**)&d_WtFw, g_WtFw);
    float* d_WtUp; cudaGetSymbolAddress((void**)&d_WtUp, g_WtUp);

    // ---- CSR build (R4 structure) ----
    k_hist0<<<(SCAN_L + 255) / 256, 256>>>();
    k_hist<<<(NE_UP + 255) / 256, 256>>>(eidx + NE_UP, NE_UP, 0);
    for (int il = 0; il < NLY; il++)
        k_hist<<<(NE_L + 255) / 256, 256>>>(einner + (size_t)il * 2 * NE_L + NE_L, NE_L, 1 + il);
    for (int il = 0; il < NLY; il++)
        k_hist<<<(NE_L + 255) / 256, 256>>>(efw + (size_t)il * 2 * NE_L + NE_L, NE_L, 5 + il);
    k_scan1<<<SCAN_NB, 256>>>();
    k_scan2<<<1, 1024>>>();
    k_scan3<<<SCAN_NB, 256>>>();
    k_dinv<<<(SCAN_L + 255) / 256, 256>>>();
    k_cursor<<<(SCAN_L + 255) / 256, 256>>>();
    k_fill<<<(NE_UP + 255) / 256, 256>>>(eidx, eidx + NE_UP, NE_UP, 0);
    for (int il = 0; il < NLY; il++)
        k_fill<<<(NE_L + 255) / 256, 256>>>(einner + (size_t)il * 2 * NE_L,
                                            einner + (size_t)il * 2 * NE_L + NE_L, NE_L, 1 + il);
    for (int il = 0; il < NLY; il++)
        k_fill<<<(NE_L + 255) / 256, 256>>>(efw + (size_t)il * 2 * NE_L,
                                            efw + (size_t)il * 2 * NE_L + NE_L, NE_L, 5 + il);
    k_build<<<(Nn + 255) / 256, 256>>>(layers);
    k_transpose_h<<<(FA * 256 + 255) / 256, 256>>>(W_in, d_WtIn, FA);
    k_transpose_h<<<(FA * 256 + 255) / 256, 256>>>(W_fw, d_WtFw, FA);
    k_transpose<<<(16 * 256 + 255) / 256, 256>>>(W_up, d_WtUp, 16);

    const int GX = (Nn + 127) / 128;

    // ---- up conv ----
    k_up_gather<<<(Nn * 4 + 255) / 256, 256>>>(x16);
    k_mma_gemm_up<<<dim3(GX, 2), 256>>>(b_up);

    auto conv = [&](int slot, int mask, const __half* Wt, const float* bb, int to_pi) {
        k_gather<<<(Nn + 7) / 8, 256>>>(stat, slot, mask);
        k_mma_gemm<<<dim3(GX, 2), 256>>>(Wt, bb, mask, to_pi);
    };

    for (int p = 0; p < 2; p++) {
        for (int il = 0; il < 3; il++) {
            conv(1 + il, il, d_WtIn, b_in, 0);          // inner -> rows(il)
            conv(5 + il, il + 1, d_WtFw, b_fw, 0);      // fw    -> rows(il+1)
        }
        conv(4, -1, d_WtIn, b_in, 1);                   // full -> pi
        k_copy_rows<<<(Nn + 3) / 4, 256>>>(3);
        k_relu4<<<(Nn * F / 4 + 255) / 256, 256>>>();
        for (int il = 3; il >= 0; il--) {
            if (il >= 1) k_copy_rows<<<(Nn + 3) / 4, 256>>>(il - 1);
            conv(1 + il, il, d_WtIn, b_in, 0);
        }
        k_relu4<<<(Nn * F / 4 + 255) / 256, 256>>>();
    }

    k_pool_init<<<1, 64>>>(b_lin, out);
    k_pool<<<(Nn * 32 + 255) / 256, 256>>>(batch, W_lin, out);
}

// round 12
// speedup vs baseline: 1.6315x; 1.2000x over previous
#include <cuda_runtime.h>
#include <cuda_fp16.h>
#include <cstdint>

#define Nn    100000
#define F     256
#define FS    32
#define FA    288
#define NLY   4
#define NG    50
#define NE_UP 400000
#define NE_L  300000
#define NE_TOT (NE_UP + 8 * NE_L)
#define SCAN_L (9 * Nn)
#define SCAN_BLK 1024
#define SCAN_NB ((SCAN_L + SCAN_BLK - 1) / SCAN_BLK)

// ---------------- device scratch ----------------
__device__ __half g_x[(size_t)Nn * F];                // fp16 state
__device__ __half g_pi[(size_t)Nn * F];               // fp16 state
__device__ __half g_agg[(size_t)Nn * FA];             // fp16 GEMM A
__device__ float g_agg16[(size_t)Nn * 16];
__device__ float g_dinv[(size_t)SCAN_L];
__device__ int   g_hist[(size_t)SCAN_L];
__device__ int   g_rp[(size_t)SCAN_L + 1];
__device__ int   g_col[(size_t)NE_TOT];
__device__ float g_we[(size_t)NE_TOT];
__device__ int   g_bsum[SCAN_NB];
__device__ int   g_boff[SCAN_NB];
__device__ int   g_total;
__device__ int   g_rows[(size_t)NLY * Nn];
__device__ int   g_cnt[NLY];
__device__ __half g_WtIn[(size_t)256 * FA];           // fp16 W^T
__device__ __half g_WtFw[(size_t)256 * FA];
__device__ float g_WtUp[(size_t)256 * 16];

__device__ __forceinline__ uint32_t f2tf32(float f) {
    uint32_t r; asm("cvt.rna.tf32.f32 %0, %1;" : "=r"(r) : "f"(f)); return r;
}
__device__ __forceinline__ uint4 tf4(float4 v) {
    return make_uint4(f2tf32(v.x), f2tf32(v.y), f2tf32(v.z), f2tf32(v.w));
}
__device__ __forceinline__ void mma_tf32(float* d, const uint32_t* a, const uint32_t* b) {
    asm volatile(
        "mma.sync.aligned.m16n8k8.row.col.f32.tf32.tf32.f32 "
        "{%0,%1,%2,%3}, {%4,%5,%6,%7}, {%8,%9}, {%0,%1,%2,%3};"
        : "+f"(d[0]), "+f"(d[1]), "+f"(d[2]), "+f"(d[3])
        : "r"(a[0]), "r"(a[1]), "r"(a[2]), "r"(a[3]), "r"(b[0]), "r"(b[1]));
}
__device__ __forceinline__ void mma_f16(float* d, const uint32_t* a, const uint32_t* b) {
    asm volatile(
        "mma.sync.aligned.m16n8k16.row.col.f32.f16.f16.f32 "
        "{%0,%1,%2,%3}, {%4,%5,%6,%7}, {%8,%9}, {%0,%1,%2,%3};"
        : "+f"(d[0]), "+f"(d[1]), "+f"(d[2]), "+f"(d[3])
        : "r"(a[0]), "r"(a[1]), "r"(a[2]), "r"(a[3]), "r"(b[0]), "r"(b[1]));
}
__device__ __forceinline__ float4 fmaf4(float4 a, float w, float4 v) {
    a.x = fmaf(w, v.x, a.x); a.y = fmaf(w, v.y, a.y);
    a.z = fmaf(w, v.z, a.z); a.w = fmaf(w, v.w, a.w);
    return a;
}
__device__ __forceinline__ void unpack8h(uint4 r, float* a) {
    float2 f;
    f = __half22float2(*(__half2*)&r.x); a[0] = f.x; a[1] = f.y;
    f = __half22float2(*(__half2*)&r.y); a[2] = f.x; a[3] = f.y;
    f = __half22float2(*(__half2*)&r.z); a[4] = f.x; a[5] = f.y;
    f = __half22float2(*(__half2*)&r.w); a[6] = f.x; a[7] = f.y;
}
__device__ __forceinline__ uint4 pack8h(const float* a) {
    uint4 r;
    __half2 h;
    h = __floats2half2_rn(a[0], a[1]); r.x = *(uint32_t*)&h;
    h = __floats2half2_rn(a[2], a[3]); r.y = *(uint32_t*)&h;
    h = __floats2half2_rn(a[4], a[5]); r.z = *(uint32_t*)&h;
    h = __floats2half2_rn(a[6], a[7]); r.w = *(uint32_t*)&h;
    return r;
}

// ---------------- CSR build (R4-identical) ----------------
__global__ void k_hist0() {
    int i = blockIdx.x * blockDim.x + threadIdx.x;
    if (i < SCAN_L) g_hist[i] = 0;
    if (i < NLY) g_cnt[i] = 0;
}
__global__ void k_hist(const int* __restrict__ dst, int nE, int slot) {
    int i = blockIdx.x * blockDim.x + threadIdx.x;
    if (i >= nE) return;
    atomicAdd(&g_hist[(size_t)slot * Nn + dst[i]], 1);
}
__global__ void k_scan1() {
    __shared__ int ws[8];
    int t = threadIdx.x;
    int base = blockIdx.x * SCAN_BLK + t * 4;
    int v[4], s = 0;
#pragma unroll
    for (int j = 0; j < 4; j++) {
        v[j] = (base + j < SCAN_L) ? g_hist[base + j] : 0;
        s += v[j];
    }
    int lane = t & 31, w = t >> 5;
    int inc = s;
#pragma unroll
    for (int o = 1; o < 32; o <<= 1) {
        int x = __shfl_up_sync(0xffffffffu, inc, o);
        if (lane >= o) inc += x;
    }
    if (lane == 31) ws[w] = inc;
    __syncthreads();
    if (t < 8) {
        int x = ws[t];
#pragma unroll
        for (int o = 1; o < 8; o <<= 1) {
            int y = __shfl_up_sync(0xffu, x, o);
            if (t >= o) x += y;
        }
        ws[t] = x;
    }
    __syncthreads();
    int run = inc - s + (w > 0 ? ws[w - 1] : 0);
#pragma unroll
    for (int j = 0; j < 4; j++) {
        if (base + j < SCAN_L) g_rp[base + j] = run;
        run += v[j];
    }
    __syncthreads();
    if (t == 255) g_bsum[blockIdx.x] = ws[7];
}
__global__ void k_scan2() {
    __shared__ int ws[32];
    int t = threadIdx.x;
    int v = (t < SCAN_NB) ? g_bsum[t] : 0;
    int lane = t & 31, w = t >> 5;
    int inc = v;
#pragma unroll
    for (int o = 1; o < 32; o <<= 1) {
        int x = __shfl_up_sync(0xffffffffu, inc, o);
        if (lane >= o) inc += x;
    }
    if (lane == 31) ws[w] = inc;
    __syncthreads();
    if (t < 32) {
        int x = ws[t];
#pragma unroll
        for (int o = 1; o < 32; o <<= 1) {
            int y = __shfl_up_sync(0xffffffffu, x, o);
            if (t >= o) x += y;
        }
        ws[t] = x;
    }
    __syncthreads();
    int excl = inc - v + (w > 0 ? ws[w - 1] : 0);
    if (t < SCAN_NB) g_boff[t] = excl;
    if (t == SCAN_NB - 1) g_total = excl + v;
}
__global__ void k_scan3() {
    int t = threadIdx.x;
    int off = g_boff[blockIdx.x];
    int base = blockIdx.x * SCAN_BLK + t * 4;
#pragma unroll
    for (int j = 0; j < 4; j++)
        if (base + j < SCAN_L) g_rp[base + j] += off;
    if (blockIdx.x == 0 && t == 0) g_rp[SCAN_L] = g_total;
}
__global__ void k_dinv() {
    int i = blockIdx.x * blockDim.x + threadIdx.x;
    if (i < SCAN_L) g_dinv[i] = rsqrtf((float)(g_hist[i] + 1));
}
__global__ void k_cursor() {
    int i = blockIdx.x * blockDim.x + threadIdx.x;
    if (i < SCAN_L) g_hist[i] = g_rp[i];
}
__global__ void k_fill(const int* __restrict__ src, const int* __restrict__ dst,
                       int nE, int slot) {
    int e = blockIdx.x * blockDim.x + threadIdx.x;
    if (e >= nE) return;
    int d = dst[e], s = src[e];
    int pos = atomicAdd(&g_hist[(size_t)slot * Nn + d], 1);
    g_col[pos] = s;
    g_we[pos] = g_dinv[(size_t)slot * Nn + s];
}
__global__ void k_build(const int* __restrict__ layers) {
    int n = blockIdx.x * blockDim.x + threadIdx.x;
    if (n >= Nn) return;
    int il = layers[n];
    int p = atomicAdd(&g_cnt[il], 1);
    g_rows[(size_t)il * Nn + p] = n;
}
__global__ void k_transpose_h(const float* __restrict__ W, __half* __restrict__ Wt, int K) {
    int i = blockIdx.x * blockDim.x + threadIdx.x;
    if (i >= K * 256) return;
    int k = i >> 8, n = i & 255;
    Wt[(size_t)n * K + k] = __float2half_rn(W[i]);
}
__global__ void k_transpose(const float* __restrict__ W, float* __restrict__ Wt, int K) {
    int i = blockIdx.x * blockDim.x + threadIdx.x;
    if (i >= K * 256) return;
    int k = i >> 8, n = i & 255;
    Wt[(size_t)n * K + k] = W[i];
}

// ---------------- up conv (fp32 gather + tf32 GEMM -> fp16 x) ----------------
__global__ void k_up_gather(const float* __restrict__ x16) {
    int i = blockIdx.x * blockDim.x + threadIdx.x;
    if (i >= Nn * 4) return;
    int n = i >> 2, q = i & 3;
    float dd = g_dinv[n];
    int r0 = g_rp[n], r1 = g_rp[n + 1];
    float4 a = ((const float4*)(x16 + (size_t)n * 16))[q];
    a.x *= dd; a.y *= dd; a.z *= dd; a.w *= dd;
    for (int e = r0; e < r1; e++) {
        int s = g_col[e];
        float wgt = g_we[e];
        a = fmaf4(a, wgt, ((const float4*)(x16 + (size_t)s * 16))[q]);
    }
    a.x *= dd; a.y *= dd; a.z *= dd; a.w *= dd;
    ((float4*)(g_agg16 + (size_t)n * 16))[q] = a;
}

#define ASTRIDE 36
__global__ void __launch_bounds__(256)
k_mma_gemm_up(const float* __restrict__ bias) {
    __shared__ uint32_t As[128 * ASTRIDE];
    __shared__ uint32_t Bs[128 * ASTRIDE];
    int row0 = blockIdx.x * 128;
    int colb = blockIdx.y * 128;
    int tid = threadIdx.x, wid = tid >> 5, lane = tid & 31;
    int wm = (wid >> 2) * 64, wn = (wid & 3) * 32;
    int q = lane >> 2, t = lane & 3;

    float acc[4][4][4];
#pragma unroll
    for (int i = 0; i < 4; i++)
#pragma unroll
        for (int j = 0; j < 4; j++)
#pragma unroll
            for (int k = 0; k < 4; k++) acc[i][j][k] = 0.f;
    {
        int idx = tid;
        for (int i = 0; i < 2; i++) {
            int e = idx + i * 256;
            int m = e >> 2, k4 = e & 3;
            int g = row0 + m;
            uint4 v = make_uint4(0, 0, 0, 0);
            if (g < Nn) v = tf4(*(const float4*)(g_agg16 + (size_t)g * 16 + k4 * 4));
            *(uint4*)(&As[m * ASTRIDE + k4 * 4]) = v;
        }
        for (int i = 0; i < 2; i++) {
            int e = idx + i * 256;
            int n = e >> 2, k4 = e & 3;
            float4 f = *(const float4*)(g_WtUp + (size_t)(colb + n) * 16 + k4 * 4);
            *(uint4*)(&Bs[n * ASTRIDE + k4 * 4]) = tf4(f);
        }
    }
    __syncthreads();
#pragma unroll
    for (int ks = 0; ks < 2; ks++) {
        int kc = ks * 8;
        uint32_t af[4][4];
#pragma unroll
        for (int mt = 0; mt < 4; mt++) {
            int r = wm + mt * 16 + q;
            af[mt][0] = As[r * ASTRIDE + kc + t];
            af[mt][1] = As[(r + 8) * ASTRIDE + kc + t];
            af[mt][2] = As[r * ASTRIDE + kc + t + 4];
            af[mt][3] = As[(r + 8) * ASTRIDE + kc + t + 4];
        }
        uint32_t bf[4][2];
#pragma unroll
        for (int nt = 0; nt < 4; nt++) {
            int n = wn + nt * 8 + q;
            bf[nt][0] = Bs[n * ASTRIDE + kc + t];
            bf[nt][1] = Bs[n * ASTRIDE + kc + t + 4];
        }
#pragma unroll
        for (int mt = 0; mt < 4; mt++)
#pragma unroll
            for (int nt = 0; nt < 4; nt++)
                mma_tf32(acc[mt][nt], af[mt], bf[nt]);
    }
#pragma unroll
    for (int mt = 0; mt < 4; mt++) {
        int n0 = row0 + wm + mt * 16 + q;
        int n1 = n0 + 8;
#pragma unroll
        for (int nt = 0; nt < 4; nt++) {
            int col = colb + wn + nt * 8 + t * 2;
            float b0 = bias[col], b1 = bias[col + 1];
            if (n0 < Nn) {
                __half2 h = __floats2half2_rn(acc[mt][nt][0] + b0, acc[mt][nt][1] + b1);
                ((uint32_t*)(g_x + (size_t)n0 * F))[col >> 1] = *(uint32_t*)&h;
            }
            if (n1 < Nn) {
                __half2 h = __floats2half2_rn(acc[mt][nt][2] + b0, acc[mt][nt][3] + b1);
                ((uint32_t*)(g_x + (size_t)n1 * F))[col >> 1] = *(uint32_t*)&h;
            }
        }
    }
}

// ---------------- gather: fp16 x -> fp16 agg (fp32 accumulation) ----------------
__global__ void __launch_bounds__(256)
k_gather(const float* __restrict__ stat, int slot, int mask_il) {
    int w = threadIdx.x >> 5, lane = threadIdx.x & 31;
    int idx = blockIdx.x * 8 + w;
    int cnt = (mask_il >= 0) ? g_cnt[mask_il] : Nn;
    if (idx >= cnt) return;
    int n = (mask_il >= 0) ? g_rows[(size_t)mask_il * Nn + idx] : idx;
    size_t sb = (size_t)slot * Nn;
    float dd = g_dinv[sb + n];
    int e = g_rp[sb + n], e1 = g_rp[sb + n + 1];

    // x row: 256 fp16 = 32 uint4; lane owns cols 8*lane..8*lane+7
    float a[8];
    unpack8h(((const uint4*)(g_x + (size_t)n * F))[lane], a);
    float st[4] = {0.f, 0.f, 0.f, 0.f};
    if (lane < 8) {
        float4 f = ((const float4*)(stat + (size_t)n * FS))[lane];
        st[0] = f.x; st[1] = f.y; st[2] = f.z; st[3] = f.w;
    }
#pragma unroll
    for (int j = 0; j < 8; j++) a[j] *= dd;
#pragma unroll
    for (int j = 0; j < 4; j++) st[j] *= dd;

    int sn = 0; float wn_ = 0.f;
    if (e < e1) { sn = g_col[e]; wn_ = g_we[e]; }
    while (e < e1) {
        int s = sn; float wgt = wn_;
        if (e + 1 < e1) { sn = g_col[e + 1]; wn_ = g_we[e + 1]; }
        float xs[8];
        unpack8h(((const uint4*)(g_x + (size_t)s * F))[lane], xs);
#pragma unroll
        for (int j = 0; j < 8; j++) a[j] = fmaf(wgt, xs[j], a[j]);
        if (lane < 8) {
            float4 f = ((const float4*)(stat + (size_t)s * FS))[lane];
            st[0] = fmaf(wgt, f.x, st[0]); st[1] = fmaf(wgt, f.y, st[1]);
            st[2] = fmaf(wgt, f.z, st[2]); st[3] = fmaf(wgt, f.w, st[3]);
        }
        e++;
    }
#pragma unroll
    for (int j = 0; j < 8; j++) a[j] *= dd;
#pragma unroll
    for (int j = 0; j < 4; j++) st[j] *= dd;

    __half* ag = g_agg + (size_t)n * FA;
    ((uint4*)ag)[lane] = pack8h(a);          // cols 8*lane..+8
    if (lane < 8) {
        __half2 h0 = __floats2half2_rn(st[0], st[1]);
        __half2 h1 = __floats2half2_rn(st[2], st[3]);
        ((uint2*)(ag + 256))[lane] = make_uint2(*(uint32_t*)&h0, *(uint32_t*)&h1);
    }
}

// ---------------- fp16 GEMM: 256 thr, M=128 x N=128, m16n8k16 (R11-proven) ----------------
#define BST 20
__global__ void __launch_bounds__(256)
k_mma_gemm(const __half* __restrict__ Wt, const float* __restrict__ bias,
           int mask_il, int to_pi) {
    __shared__ uint32_t As[128 * BST];
    __shared__ uint32_t Bs[128 * BST];

    int cnt = (mask_il >= 0) ? g_cnt[mask_il] : Nn;
    const int* list = (mask_il >= 0) ? (g_rows + (size_t)mask_il * Nn) : nullptr;
    int row0 = blockIdx.x * 128;
    if (row0 >= cnt) return;
    int colb = blockIdx.y * 128;

    int tid = threadIdx.x, wid = tid >> 5, lane = tid & 31;
    int wm = (wid >> 2) * 64;
    int wn = (wid & 3) * 32;
    int q = lane >> 2, t = lane & 3;

    float acc[4][4][4];
#pragma unroll
    for (int i = 0; i < 4; i++)
#pragma unroll
        for (int j = 0; j < 4; j++)
#pragma unroll
            for (int k = 0; k < 4; k++) acc[i][j][k] = 0.f;

    int amrow[2];
#pragma unroll
    for (int i = 0; i < 2; i++) {
        int m = (tid + i * 256) >> 2;
        int g = row0 + m;
        amrow[i] = (g < cnt) ? (list ? list[g] : g) : (list ? list[row0] : row0);
    }

    for (int kt = 0; kt < FA; kt += 32) {
#pragma unroll
        for (int i = 0; i < 2; i++) {
            int idx = tid + i * 256;
            int m = idx >> 2, k4 = idx & 3;
            uint4 v = *(const uint4*)((const uint32_t*)(g_agg + (size_t)amrow[i] * FA)
                                      + (kt >> 1) + k4 * 4);
            *(uint4*)(&As[m * BST + k4 * 4]) = v;
        }
#pragma unroll
        for (int i = 0; i < 2; i++) {
            int idx = tid + i * 256;
            int n = idx >> 2, k4 = idx & 3;
            uint4 v = *(const uint4*)((const uint32_t*)(Wt + (size_t)(colb + n) * FA)
                                      + (kt >> 1) + k4 * 4);
            *(uint4*)(&Bs[n * BST + k4 * 4]) = v;
        }
        __syncthreads();
#pragma unroll
        for (int ks = 0; ks < 2; ks++) {
            int kc = ks * 8;
            uint32_t af[4][4];
#pragma unroll
            for (int mt = 0; mt < 4; mt++) {
                int r = wm + mt * 16 + q;
                af[mt][0] = As[r * BST + kc + t];
                af[mt][1] = As[(r + 8) * BST + kc + t];
                af[mt][2] = As[r * BST + kc + t + 4];
                af[mt][3] = As[(r + 8) * BST + kc + t + 4];
            }
            uint32_t bf[4][2];
#pragma unroll
            for (int nt = 0; nt < 4; nt++) {
                int n = wn + nt * 8 + q;
                bf[nt][0] = Bs[n * BST + kc + t];
                bf[nt][1] = Bs[n * BST + kc + t + 4];
            }
#pragma unroll
            for (int mt = 0; mt < 4; mt++)
#pragma unroll
                for (int nt = 0; nt < 4; nt++)
                    mma_f16(acc[mt][nt], af[mt], bf[nt]);
        }
        __syncthreads();
    }

    __half* outb = to_pi ? g_pi : g_x;
#pragma unroll
    for (int mt = 0; mt < 4; mt++) {
        int g0 = row0 + wm + mt * 16 + q;
        int g1 = g0 + 8;
        int n0 = (g0 < cnt) ? (list ? list[g0] : g0) : -1;
        int n1 = (g1 < cnt) ? (list ? list[g1] : g1) : -1;
#pragma unroll
        for (int nt = 0; nt < 4; nt++) {
            int col = colb + wn + nt * 8 + t * 2;
            float b0 = bias[col], b1 = bias[col + 1];
            if (n0 >= 0) {
                __half2 h = __floats2half2_rn(acc[mt][nt][0] + b0, acc[mt][nt][1] + b1);
                ((uint32_t*)(outb + (size_t)n0 * F))[col >> 1] = *(uint32_t*)&h;
            }
            if (n1 >= 0) {
                __half2 h = __floats2half2_rn(acc[mt][nt][2] + b0, acc[mt][nt][3] + b1);
                ((uint32_t*)(outb + (size_t)n1 * F))[col >> 1] = *(uint32_t*)&h;
            }
        }
    }
}

// ---------------- misc (fp16) ----------------
__global__ void k_copy_rows(int il) {   // 256 thr = 8 rows x 32 uint4
    int c = threadIdx.x & 31, r = threadIdx.x >> 5;
    int idx = blockIdx.x * 8 + r;
    if (idx >= g_cnt[il]) return;
    int n = g_rows[(size_t)il * Nn + idx];
    ((uint4*)(g_x + (size_t)n * F))[c] = ((const uint4*)(g_pi + (size_t)n * F))[c];
}
__global__ void k_relu4() {             // uint4 = 8 fp16
    int i = blockIdx.x * blockDim.x + threadIdx.x;
    if (i >= Nn * F / 8) return;
    uint4 v = ((uint4*)g_x)[i];
    __half2 z = __float2half2_rn(0.f);
    *(__half2*)&v.x = __hmax2(*(__half2*)&v.x, z);
    *(__half2*)&v.y = __hmax2(*(__half2*)&v.y, z);
    *(__half2*)&v.z = __hmax2(*(__half2*)&v.z, z);
    *(__half2*)&v.w = __hmax2(*(__half2*)&v.w, z);
    ((uint4*)g_x)[i] = v;
}
__global__ void k_pool_init(const float* __restrict__ bl, float* __restrict__ out) {
    int g = threadIdx.x;
    if (g < NG) out[g] = bl[0];
}
__global__ void k_pool(const int* __restrict__ batch, const float* __restrict__ Wl,
                       float* __restrict__ out) {
    int w = (blockIdx.x * blockDim.x + threadIdx.x) >> 5;
    int lane = threadIdx.x & 31;
    if (w >= Nn) return;
    const uint32_t* xr = (const uint32_t*)(g_x + (size_t)w * F);
    float s = 0.f;
    for (int c = lane; c < 128; c += 32) {
        float2 f = __half22float2(*(const __half2*)&xr[c]);
        s += f.x * Wl[2 * c] + f.y * Wl[2 * c + 1];
    }
#pragma unroll
    for (int o = 16; o; o >>= 1) s += __shfl_down_sync(0xffffffffu, s, o);
    if (lane == 0) atomicAdd(&out[batch[w]], s);
}

// ---------------- orchestration (R4/R11-identical sequence) ----------------
extern "C" void kernel_launch(void* const* d_in, const int* in_sizes, int n_in,
                              void* d_out, int out_size) {
    const float* x16    = (const float*)d_in[0];
    const float* stat   = (const float*)d_in[1];
    const int*   eidx   = (const int*)d_in[2];
    const int*   einner = (const int*)d_in[3];
    const int*   efw    = (const int*)d_in[4];
    const int*   layers = (const int*)d_in[6];
    const int*   batch  = (const int*)d_in[7];
    const float* W_up  = (const float*)d_in[8];
    const float* b_up  = (const float*)d_in[9];
    const float* W_in  = (const float*)d_in[10];
    const float* b_in  = (const float*)d_in[11];
    const float* W_fw  = (const float*)d_in[12];
    const float* b_fw  = (const float*)d_in[13];
    const float* W_lin = (const float*)d_in[14];
    const float* b_lin = (const float*)d_in[15];
    float* out = (float*)d_out;

    __half* d_WtIn; cudaGetSymbolAddress((void**)&d_WtIn, g_WtIn);
    __half* d_WtFw; cudaGetSymbolAddress((void**)&d_WtFw, g_WtFw);
    float* d_WtUp; cudaGetSymbolAddress((void**)&d_WtUp, g_WtUp);

    // ---- CSR build ----
    k_hist0<<<(SCAN_L + 255) / 256, 256>>>();
    k_hist<<<(NE_UP + 255) / 256, 256>>>(eidx + NE_UP, NE_UP, 0);
    for (int il = 0; il < NLY; il++)
        k_hist<<<(NE_L + 255) / 256, 256>>>(einner + (size_t)il * 2 * NE_L + NE_L, NE_L, 1 + il);
    for (int il = 0; il < NLY; il++)
        k_hist<<<(NE_L + 255) / 256, 256>>>(efw + (size_t)il * 2 * NE_L + NE_L, NE_L, 5 + il);
    k_scan1<<<SCAN_NB, 256>>>();
    k_scan2<<<1, 1024>>>();
    k_scan3<<<SCAN_NB, 256>>>();
    k_dinv<<<(SCAN_L + 255) / 256, 256>>>();
    k_cursor<<<(SCAN_L + 255) / 256, 256>>>();
    k_fill<<<(NE_UP + 255) / 256, 256>>>(eidx, eidx + NE_UP, NE_UP, 0);
    for (int il = 0; il < NLY; il++)
        k_fill<<<(NE_L + 255) / 256, 256>>>(einner + (size_t)il * 2 * NE_L,
                                            einner + (size_t)il * 2 * NE_L + NE_L, NE_L, 1 + il);
    for (int il = 0; il < NLY; il++)
        k_fill<<<(NE_L + 255) / 256, 256>>>(efw + (size_t)il * 2 * NE_L,
                                            efw + (size_t)il * 2 * NE_L + NE_L, NE_L, 5 + il);
    k_build<<<(Nn + 255) / 256, 256>>>(layers);
    k_transpose_h<<<(FA * 256 + 255) / 256, 256>>>(W_in, d_WtIn, FA);
    k_transpose_h<<<(FA * 256 + 255) / 256, 256>>>(W_fw, d_WtFw, FA);
    k_transpose<<<(16 * 256 + 255) / 256, 256>>>(W_up, d_WtUp, 16);

    const int GX = (Nn + 127) / 128;

    // ---- up conv ----
    k_up_gather<<<(Nn * 4 + 255) / 256, 256>>>(x16);
    k_mma_gemm_up<<<dim3(GX, 2), 256>>>(b_up);

    auto conv = [&](int slot, int mask, const __half* Wt, const float* bb, int to_pi) {
        k_gather<<<(Nn + 7) / 8, 256>>>(stat, slot, mask);
        k_mma_gemm<<<dim3(GX, 2), 256>>>(Wt, bb, mask, to_pi);
    };

    for (int p = 0; p < 2; p++) {
        for (int il = 0; il < 3; il++) {
            conv(1 + il, il, d_WtIn, b_in, 0);          // inner -> rows(il)
            conv(5 + il, il + 1, d_WtFw, b_fw, 0);      // fw    -> rows(il+1)
        }
        conv(4, -1, d_WtIn, b_in, 1);                   // full -> pi
        k_copy_rows<<<(Nn + 7) / 8, 256>>>(3);
        k_relu4<<<(Nn * F / 8 + 255) / 256, 256>>>();
        for (int il = 3; il >= 0; il--) {
            if (il >= 1) k_copy_rows<<<(Nn + 7) / 8, 256>>>(il - 1);
            conv(1 + il, il, d_WtIn, b_in, 0);
        }
        k_relu4<<<(Nn * F / 8 + 255) / 256, 256>>>();
    }

    k_pool_init<<<1, 64>>>(b_lin, out);
    k_pool<<<(Nn * 32 + 255) / 256, 256>>>(batch, W_lin, out);
}

// round 13
// speedup vs baseline: 1.6485x; 1.0104x over previous
#include <cuda_runtime.h>
#include <cuda_fp16.h>
#include <cstdint>

#define Nn    100000
#define F     256
#define FS    32
#define FA    288
#define NLY   4
#define NG    50
#define NE_UP 400000
#define NE_L  300000
#define NE_TOT (NE_UP + 8 * NE_L)
#define SCAN_L (9 * Nn)
#define SCAN_BLK 1024
#define SCAN_NB ((SCAN_L + SCAN_BLK - 1) / SCAN_BLK)

// ---------------- device scratch ----------------
__device__ __half g_x[(size_t)Nn * F];
__device__ __half g_pi[(size_t)Nn * F];
__device__ __half g_agg[(size_t)Nn * FA];
__device__ __half g_stat_h[(size_t)Nn * FS];
__device__ float g_agg16[(size_t)Nn * 16];
__device__ float g_dinv[(size_t)SCAN_L];
__device__ int   g_hist[(size_t)SCAN_L];
__device__ int   g_rp[(size_t)SCAN_L + 1];
__device__ int   g_col[(size_t)NE_TOT];
__device__ float g_we[(size_t)NE_TOT];
__device__ int   g_bsum[SCAN_NB];
__device__ int   g_boff[SCAN_NB];
__device__ int   g_total;
__device__ int   g_rows[(size_t)NLY * Nn];
__device__ int   g_cnt[NLY];
__device__ __half g_WtIn[(size_t)256 * FA];
__device__ __half g_WtFw[(size_t)256 * FA];
__device__ float g_WtUp[(size_t)256 * 16];

__device__ __forceinline__ uint32_t f2tf32(float f) {
    uint32_t r; asm("cvt.rna.tf32.f32 %0, %1;" : "=r"(r) : "f"(f)); return r;
}
__device__ __forceinline__ uint4 tf4(float4 v) {
    return make_uint4(f2tf32(v.x), f2tf32(v.y), f2tf32(v.z), f2tf32(v.w));
}
__device__ __forceinline__ void mma_tf32(float* d, const uint32_t* a, const uint32_t* b) {
    asm volatile(
        "mma.sync.aligned.m16n8k8.row.col.f32.tf32.tf32.f32 "
        "{%0,%1,%2,%3}, {%4,%5,%6,%7}, {%8,%9}, {%0,%1,%2,%3};"
        : "+f"(d[0]), "+f"(d[1]), "+f"(d[2]), "+f"(d[3])
        : "r"(a[0]), "r"(a[1]), "r"(a[2]), "r"(a[3]), "r"(b[0]), "r"(b[1]));
}
__device__ __forceinline__ void mma_f16(float* d, const uint32_t* a, const uint32_t* b) {
    asm volatile(
        "mma.sync.aligned.m16n8k16.row.col.f32.f16.f16.f32 "
        "{%0,%1,%2,%3}, {%4,%5,%6,%7}, {%8,%9}, {%0,%1,%2,%3};"
        : "+f"(d[0]), "+f"(d[1]), "+f"(d[2]), "+f"(d[3])
        : "r"(a[0]), "r"(a[1]), "r"(a[2]), "r"(a[3]), "r"(b[0]), "r"(b[1]));
}
__device__ __forceinline__ float4 fmaf4(float4 a, float w, float4 v) {
    a.x = fmaf(w, v.x, a.x); a.y = fmaf(w, v.y, a.y);
    a.z = fmaf(w, v.z, a.z); a.w = fmaf(w, v.w, a.w);
    return a;
}
__device__ __forceinline__ void unpack8h(uint4 r, float* a) {
    float2 f;
    f = __half22float2(*(__half2*)&r.x); a[0] = f.x; a[1] = f.y;
    f = __half22float2(*(__half2*)&r.y); a[2] = f.x; a[3] = f.y;
    f = __half22float2(*(__half2*)&r.z); a[4] = f.x; a[5] = f.y;
    f = __half22float2(*(__half2*)&r.w); a[6] = f.x; a[7] = f.y;
}
__device__ __forceinline__ void unpack4h(uint2 r, float* a) {
    float2 f;
    f = __half22float2(*(__half2*)&r.x); a[0] = f.x; a[1] = f.y;
    f = __half22float2(*(__half2*)&r.y); a[2] = f.x; a[3] = f.y;
}
__device__ __forceinline__ uint4 pack8h(const float* a) {
    uint4 r;
    __half2 h;
    h = __floats2half2_rn(a[0], a[1]); r.x = *(uint32_t*)&h;
    h = __floats2half2_rn(a[2], a[3]); r.y = *(uint32_t*)&h;
    h = __floats2half2_rn(a[4], a[5]); r.z = *(uint32_t*)&h;
    h = __floats2half2_rn(a[6], a[7]); r.w = *(uint32_t*)&h;
    return r;
}

// ---------------- CSR build ----------------
__global__ void k_hist0() {
    int i = blockIdx.x * blockDim.x + threadIdx.x;
    if (i < SCAN_L) g_hist[i] = 0;
    if (i < NLY) g_cnt[i] = 0;
}
__global__ void k_hist(const int* __restrict__ dst, int nE, int slot) {
    int i = blockIdx.x * blockDim.x + threadIdx.x;
    if (i >= nE) return;
    atomicAdd(&g_hist[(size_t)slot * Nn + dst[i]], 1);
}
__global__ void k_scan1() {
    __shared__ int ws[8];
    int t = threadIdx.x;
    int base = blockIdx.x * SCAN_BLK + t * 4;
    int v[4], s = 0;
#pragma unroll
    for (int j = 0; j < 4; j++) {
        v[j] = (base + j < SCAN_L) ? g_hist[base + j] : 0;
        s += v[j];
    }
    int lane = t & 31, w = t >> 5;
    int inc = s;
#pragma unroll
    for (int o = 1; o < 32; o <<= 1) {
        int x = __shfl_up_sync(0xffffffffu, inc, o);
        if (lane >= o) inc += x;
    }
    if (lane == 31) ws[w] = inc;
    __syncthreads();
    if (t < 8) {
        int x = ws[t];
#pragma unroll
        for (int o = 1; o < 8; o <<= 1) {
            int y = __shfl_up_sync(0xffu, x, o);
            if (t >= o) x += y;
        }
        ws[t] = x;
    }
    __syncthreads();
    int run = inc - s + (w > 0 ? ws[w - 1] : 0);
#pragma unroll
    for (int j = 0; j < 4; j++) {
        if (base + j < SCAN_L) g_rp[base + j] = run;
        run += v[j];
    }
    __syncthreads();
    if (t == 255) g_bsum[blockIdx.x] = ws[7];
}
__global__ void k_scan2() {
    __shared__ int ws[32];
    int t = threadIdx.x;
    int v = (t < SCAN_NB) ? g_bsum[t] : 0;
    int lane = t & 31, w = t >> 5;
    int inc = v;
#pragma unroll
    for (int o = 1; o < 32; o <<= 1) {
        int x = __shfl_up_sync(0xffffffffu, inc, o);
        if (lane >= o) inc += x;
    }
    if (lane == 31) ws[w] = inc;
    __syncthreads();
    if (t < 32) {
        int x = ws[t];
#pragma unroll
        for (int o = 1; o < 32; o <<= 1) {
            int y = __shfl_up_sync(0xffffffffu, x, o);
            if (t >= o) x += y;
        }
        ws[t] = x;
    }
    __syncthreads();
    int excl = inc - v + (w > 0 ? ws[w - 1] : 0);
    if (t < SCAN_NB) g_boff[t] = excl;
    if (t == SCAN_NB - 1) g_total = excl + v;
}
__global__ void k_scan3() {
    int t = threadIdx.x;
    int off = g_boff[blockIdx.x];
    int base = blockIdx.x * SCAN_BLK + t * 4;
#pragma unroll
    for (int j = 0; j < 4; j++)
        if (base + j < SCAN_L) g_rp[base + j] += off;
    if (blockIdx.x == 0 && t == 0) g_rp[SCAN_L] = g_total;
}
__global__ void k_dinv() {
    int i = blockIdx.x * blockDim.x + threadIdx.x;
    if (i < SCAN_L) g_dinv[i] = rsqrtf((float)(g_hist[i] + 1));
}
__global__ void k_cursor() {
    int i = blockIdx.x * blockDim.x + threadIdx.x;
    if (i < SCAN_L) g_hist[i] = g_rp[i];
}
__global__ void k_fill(const int* __restrict__ src, const int* __restrict__ dst,
                       int nE, int slot) {
    int e = blockIdx.x * blockDim.x + threadIdx.x;
    if (e >= nE) return;
    int d = dst[e], s = src[e];
    int pos = atomicAdd(&g_hist[(size_t)slot * Nn + d], 1);
    g_col[pos] = s;
    g_we[pos] = g_dinv[(size_t)slot * Nn + s];
}
__global__ void k_build(const int* __restrict__ layers) {
    int n = blockIdx.x * blockDim.x + threadIdx.x;
    if (n >= Nn) return;
    int il = layers[n];
    int p = atomicAdd(&g_cnt[il], 1);
    g_rows[(size_t)il * Nn + p] = n;
}
__global__ void k_transpose_h(const float* __restrict__ W, __half* __restrict__ Wt, int K) {
    int i = blockIdx.x * blockDim.x + threadIdx.x;
    if (i >= K * 256) return;
    int k = i >> 8, n = i & 255;
    Wt[(size_t)n * K + k] = __float2half_rn(W[i]);
}
__global__ void k_transpose(const float* __restrict__ W, float* __restrict__ Wt, int K) {
    int i = blockIdx.x * blockDim.x + threadIdx.x;
    if (i >= K * 256) return;
    int k = i >> 8, n = i & 255;
    Wt[(size_t)n * K + k] = W[i];
}
__global__ void k_stat_h(const float* __restrict__ stat) {
    int i = blockIdx.x * blockDim.x + threadIdx.x;
    if (i < Nn * FS) g_stat_h[i] = __float2half_rn(stat[i]);
}

// ---------------- up conv (unchanged) ----------------
__global__ void k_up_gather(const float* __restrict__ x16) {
    int i = blockIdx.x * blockDim.x + threadIdx.x;
    if (i >= Nn * 4) return;
    int n = i >> 2, q = i & 3;
    float dd = g_dinv[n];
    int r0 = g_rp[n], r1 = g_rp[n + 1];
    float4 a = ((const float4*)(x16 + (size_t)n * 16))[q];
    a.x *= dd; a.y *= dd; a.z *= dd; a.w *= dd;
    for (int e = r0; e < r1; e++) {
        int s = g_col[e];
        float wgt = g_we[e];
        a = fmaf4(a, wgt, ((const float4*)(x16 + (size_t)s * 16))[q]);
    }
    a.x *= dd; a.y *= dd; a.z *= dd; a.w *= dd;
    ((float4*)(g_agg16 + (size_t)n * 16))[q] = a;
}

#define ASTRIDE 36
__global__ void __launch_bounds__(256)
k_mma_gemm_up(const float* __restrict__ bias) {
    __shared__ uint32_t As[128 * ASTRIDE];
    __shared__ uint32_t Bs[128 * ASTRIDE];
    int row0 = blockIdx.x * 128;
    int colb = blockIdx.y * 128;
    int tid = threadIdx.x, wid = tid >> 5, lane = tid & 31;
    int wm = (wid >> 2) * 64, wn = (wid & 3) * 32;
    int q = lane >> 2, t = lane & 3;

    float acc[4][4][4];
#pragma unroll
    for (int i = 0; i < 4; i++)
#pragma unroll
        for (int j = 0; j < 4; j++)
#pragma unroll
            for (int k = 0; k < 4; k++) acc[i][j][k] = 0.f;
    {
        int idx = tid;
        for (int i = 0; i < 2; i++) {
            int e = idx + i * 256;
            int m = e >> 2, k4 = e & 3;
            int g = row0 + m;
            uint4 v = make_uint4(0, 0, 0, 0);
            if (g < Nn) v = tf4(*(const float4*)(g_agg16 + (size_t)g * 16 + k4 * 4));
            *(uint4*)(&As[m * ASTRIDE + k4 * 4]) = v;
        }
        for (int i = 0; i < 2; i++) {
            int e = idx + i * 256;
            int n = e >> 2, k4 = e & 3;
            float4 f = *(const float4*)(g_WtUp + (size_t)(colb + n) * 16 + k4 * 4);
            *(uint4*)(&Bs[n * ASTRIDE + k4 * 4]) = tf4(f);
        }
    }
    __syncthreads();
#pragma unroll
    for (int ks = 0; ks < 2; ks++) {
        int kc = ks * 8;
        uint32_t af[4][4];
#pragma unroll
        for (int mt = 0; mt < 4; mt++) {
            int r = wm + mt * 16 + q;
            af[mt][0] = As[r * ASTRIDE + kc + t];
            af[mt][1] = As[(r + 8) * ASTRIDE + kc + t];
            af[mt][2] = As[r * ASTRIDE + kc + t + 4];
            af[mt][3] = As[(r + 8) * ASTRIDE + kc + t + 4];
        }
        uint32_t bf[4][2];
#pragma unroll
        for (int nt = 0; nt < 4; nt++) {
            int n = wn + nt * 8 + q;
            bf[nt][0] = Bs[n * ASTRIDE + kc + t];
            bf[nt][1] = Bs[n * ASTRIDE + kc + t + 4];
        }
#pragma unroll
        for (int mt = 0; mt < 4; mt++)
#pragma unroll
            for (int nt = 0; nt < 4; nt++)
                mma_tf32(acc[mt][nt], af[mt], bf[nt]);
    }
#pragma unroll
    for (int mt = 0; mt < 4; mt++) {
        int n0 = row0 + wm + mt * 16 + q;
        int n1 = n0 + 8;
#pragma unroll
        for (int nt = 0; nt < 4; nt++) {
            int col = colb + wn + nt * 8 + t * 2;
            float b0 = bias[col], b1 = bias[col + 1];
            if (n0 < Nn) {
                __half2 h = __floats2half2_rn(acc[mt][nt][0] + b0, acc[mt][nt][1] + b1);
                ((uint32_t*)(g_x + (size_t)n0 * F))[col >> 1] = *(uint32_t*)&h;
            }
            if (n1 < Nn) {
                __half2 h = __floats2half2_rn(acc[mt][nt][2] + b0, acc[mt][nt][3] + b1);
                ((uint32_t*)(g_x + (size_t)n1 * F))[col >> 1] = *(uint32_t*)&h;
            }
        }
    }
}

// ---------------- gather: fp16 x/stat -> fp16 agg, edge loop unrolled x2 ----------------
__global__ void __launch_bounds__(256)
k_gather(int slot, int mask_il) {
    int w = threadIdx.x >> 5, lane = threadIdx.x & 31;
    int idx = blockIdx.x * 8 + w;
    int cnt = (mask_il >= 0) ? g_cnt[mask_il] : Nn;
    if (idx >= cnt) return;
    int n = (mask_il >= 0) ? g_rows[(size_t)mask_il * Nn + idx] : idx;
    size_t sb = (size_t)slot * Nn;
    float dd = g_dinv[sb + n];
    int e = g_rp[sb + n], e1 = g_rp[sb + n + 1];

    float a[8];
    unpack8h(((const uint4*)(g_x + (size_t)n * F))[lane], a);
    float st[4] = {0.f, 0.f, 0.f, 0.f};
    if (lane < 8)
        unpack4h(((const uint2*)(g_stat_h + (size_t)n * FS))[lane], st);
#pragma unroll
    for (int j = 0; j < 8; j++) a[j] *= dd;
#pragma unroll
    for (int j = 0; j < 4; j++) st[j] *= dd;

    // unrolled x2: two independent x-row loads in flight
    for (; e + 1 < e1; e += 2) {
        int s0 = g_col[e], s1 = g_col[e + 1];
        float w0 = g_we[e], w1 = g_we[e + 1];
        uint4 r0 = ((const uint4*)(g_x + (size_t)s0 * F))[lane];
        uint4 r1 = ((const uint4*)(g_x + (size_t)s1 * F))[lane];
        float x0[8], x1[8];
        unpack8h(r0, x0);
        unpack8h(r1, x1);
#pragma unroll
        for (int j = 0; j < 8; j++) {
            a[j] = fmaf(w0, x0[j], a[j]);
            a[j] = fmaf(w1, x1[j], a[j]);
        }
        if (lane < 8) {
            uint2 t0 = ((const uint2*)(g_stat_h + (size_t)s0 * FS))[lane];
            uint2 t1 = ((const uint2*)(g_stat_h + (size_t)s1 * FS))[lane];
            float y0[4], y1[4];
            unpack4h(t0, y0);
            unpack4h(t1, y1);
#pragma unroll
            for (int j = 0; j < 4; j++) {
                st[j] = fmaf(w0, y0[j], st[j]);
                st[j] = fmaf(w1, y1[j], st[j]);
            }
        }
    }
    if (e < e1) {
        int s = g_col[e];
        float wgt = g_we[e];
        float xs[8];
        unpack8h(((const uint4*)(g_x + (size_t)s * F))[lane], xs);
#pragma unroll
        for (int j = 0; j < 8; j++) a[j] = fmaf(wgt, xs[j], a[j]);
        if (lane < 8) {
            float ys[4];
            unpack4h(((const uint2*)(g_stat_h + (size_t)s * FS))[lane], ys);
#pragma unroll
            for (int j = 0; j < 4; j++) st[j] = fmaf(wgt, ys[j], st[j]);
        }
    }
#pragma unroll
    for (int j = 0; j < 8; j++) a[j] *= dd;
#pragma unroll
    for (int j = 0; j < 4; j++) st[j] *= dd;

    __half* ag = g_agg + (size_t)n * FA;
    ((uint4*)ag)[lane] = pack8h(a);
    if (lane < 8) {
        __half2 h0 = __floats2half2_rn(st[0], st[1]);
        __half2 h1 = __floats2half2_rn(st[2], st[3]);
        ((uint2*)(ag + 256))[lane] = make_uint2(*(uint32_t*)&h0, *(uint32_t*)&h1);
    }
}

// ---------------- fp16 GEMM, double-buffered software pipeline ----------------
#define BST 20
#define NCHUNK 9
__global__ void __launch_bounds__(256)
k_mma_gemm(const __half* __restrict__ Wt, const float* __restrict__ bias,
           int mask_il, int to_pi) {
    __shared__ uint32_t As[2][128 * BST];
    __shared__ uint32_t Bs[2][128 * BST];

    int cnt = (mask_il >= 0) ? g_cnt[mask_il] : Nn;
    const int* list = (mask_il >= 0) ? (g_rows + (size_t)mask_il * Nn) : nullptr;
    int row0 = blockIdx.x * 128;
    if (row0 >= cnt) return;
    int colb = blockIdx.y * 128;

    int tid = threadIdx.x, wid = tid >> 5, lane = tid & 31;
    int wm = (wid >> 2) * 64;
    int wn = (wid & 3) * 32;
    int q = lane >> 2, t = lane & 3;

    float acc[4][4][4];
#pragma unroll
    for (int i = 0; i < 4; i++)
#pragma unroll
        for (int j = 0; j < 4; j++)
#pragma unroll
            for (int k = 0; k < 4; k++) acc[i][j][k] = 0.f;

    // per-thread load coordinates: 2 slots cover 128 rows x 4 uint4
    int lm[2], lk[2];
    int amrow[2];
#pragma unroll
    for (int i = 0; i < 2; i++) {
        int idx = tid + i * 256;
        lm[i] = idx >> 2;
        lk[i] = idx & 3;
        int g = row0 + lm[i];
        amrow[i] = (g < cnt) ? (list ? list[g] : g) : (list ? list[row0] : row0);
    }

    // preload chunk 0 into buffer 0
#pragma unroll
    for (int i = 0; i < 2; i++) {
        uint4 va = *(const uint4*)((const uint32_t*)(g_agg + (size_t)amrow[i] * FA) + lk[i] * 4);
        *(uint4*)(&As[0][lm[i] * BST + lk[i] * 4]) = va;
        uint4 vb = *(const uint4*)((const uint32_t*)(Wt + (size_t)(colb + lm[i]) * FA) + lk[i] * 4);
        *(uint4*)(&Bs[0][lm[i] * BST + lk[i] * 4]) = vb;
    }
    __syncthreads();

#pragma unroll
    for (int c = 0; c < NCHUNK; c++) {
        int buf = c & 1;
        uint4 va[2], vb[2];
        if (c + 1 < NCHUNK) {
            int koff = (c + 1) * 16;   // u32 offset of next chunk
#pragma unroll
            for (int i = 0; i < 2; i++) {
                va[i] = *(const uint4*)((const uint32_t*)(g_agg + (size_t)amrow[i] * FA)
                                        + koff + lk[i] * 4);
                vb[i] = *(const uint4*)((const uint32_t*)(Wt + (size_t)(colb + lm[i]) * FA)
                                        + koff + lk[i] * 4);
            }
        }
        // mma on current buffer
#pragma unroll
        for (int ks = 0; ks < 2; ks++) {
            int kc = ks * 8;
            uint32_t af[4][4];
#pragma unroll
            for (int mt = 0; mt < 4; mt++) {
                int r = wm + mt * 16 + q;
                af[mt][0] = As[buf][r * BST + kc + t];
                af[mt][1] = As[buf][(r + 8) * BST + kc + t];
                af[mt][2] = As[buf][r * BST + kc + t + 4];
                af[mt][3] = As[buf][(r + 8) * BST + kc + t + 4];
            }
            uint32_t bf[4][2];
#pragma unroll
            for (int nt = 0; nt < 4; nt++) {
                int n = wn + nt * 8 + q;
                bf[nt][0] = Bs[buf][n * BST + kc + t];
                bf[nt][1] = Bs[buf][n * BST + kc + t + 4];
            }
#pragma unroll
            for (int mt = 0; mt < 4; mt++)
#pragma unroll
                for (int nt = 0; nt < 4; nt++)
                    mma_f16(acc[mt][nt], af[mt], bf[nt]);
        }
        if (c + 1 < NCHUNK) {
            int nb = buf ^ 1;
#pragma unroll
            for (int i = 0; i < 2; i++) {
                *(uint4*)(&As[nb][lm[i] * BST + lk[i] * 4]) = va[i];
                *(uint4*)(&Bs[nb][lm[i] * BST + lk[i] * 4]) = vb[i];
            }
            __syncthreads();
        }
    }

    __half* outb = to_pi ? g_pi : g_x;
#pragma unroll
    for (int mt = 0; mt < 4; mt++) {
        int g0 = row0 + wm + mt * 16 + q;
        int g1 = g0 + 8;
        int n0 = (g0 < cnt) ? (list ? list[g0] : g0) : -1;
        int n1 = (g1 < cnt) ? (list ? list[g1] : g1) : -1;
#pragma unroll
        for (int nt = 0; nt < 4; nt++) {
            int col = colb + wn + nt * 8 + t * 2;
            float b0 = bias[col], b1 = bias[col + 1];
            if (n0 >= 0) {
                __half2 h = __floats2half2_rn(acc[mt][nt][0] + b0, acc[mt][nt][1] + b1);
                ((uint32_t*)(outb + (size_t)n0 * F))[col >> 1] = *(uint32_t*)&h;
            }
            if (n1 >= 0) {
                __half2 h = __floats2half2_rn(acc[mt][nt][2] + b0, acc[mt][nt][3] + b1);
                ((uint32_t*)(outb + (size_t)n1 * F))[col >> 1] = *(uint32_t*)&h;
            }
        }
    }
}

// ---------------- misc (fp16) ----------------
__global__ void k_copy_rows(int il) {
    int c = threadIdx.x & 31, r = threadIdx.x >> 5;
    int idx = blockIdx.x * 8 + r;
    if (idx >= g_cnt[il]) return;
    int n = g_rows[(size_t)il * Nn + idx];
    ((uint4*)(g_x + (size_t)n * F))[c] = ((const uint4*)(g_pi + (size_t)n * F))[c];
}
__global__ void k_relu4() {
    int i = blockIdx.x * blockDim.x + threadIdx.x;
    if (i >= Nn * F / 8) return;
    uint4 v = ((uint4*)g_x)[i];
    __half2 z = __float2half2_rn(0.f);
    *(__half2*)&v.x = __hmax2(*(__half2*)&v.x, z);
    *(__half2*)&v.y = __hmax2(*(__half2*)&v.y, z);
    *(__half2*)&v.z = __hmax2(*(__half2*)&v.z, z);
    *(__half2*)&v.w = __hmax2(*(__half2*)&v.w, z);
    ((uint4*)g_x)[i] = v;
}
__global__ void k_pool_init(const float* __restrict__ bl, float* __restrict__ out) {
    int g = threadIdx.x;
    if (g < NG) out[g] = bl[0];
}
__global__ void k_pool(const int* __restrict__ batch, const float* __restrict__ Wl,
                       float* __restrict__ out) {
    int w = (blockIdx.x * blockDim.x + threadIdx.x) >> 5;
    int lane = threadIdx.x & 31;
    if (w >= Nn) return;
    const uint32_t* xr = (const uint32_t*)(g_x + (size_t)w * F);
    float s = 0.f;
    for (int c = lane; c < 128; c += 32) {
        float2 f = __half22float2(*(const __half2*)&xr[c]);
        s += f.x * Wl[2 * c] + f.y * Wl[2 * c + 1];
    }
#pragma unroll
    for (int o = 16; o; o >>= 1) s += __shfl_down_sync(0xffffffffu, s, o);
    if (lane == 0) atomicAdd(&out[batch[w]], s);
}

// ---------------- orchestration (R12-identical sequence) ----------------
extern "C" void kernel_launch(void* const* d_in, const int* in_sizes, int n_in,
                              void* d_out, int out_size) {
    const float* x16    = (const float*)d_in[0];
    const float* stat   = (const float*)d_in[1];
    const int*   eidx   = (const int*)d_in[2];
    const int*   einner = (const int*)d_in[3];
    const int*   efw    = (const int*)d_in[4];
    const int*   layers = (const int*)d_in[6];
    const int*   batch  = (const int*)d_in[7];
    const float* W_up  = (const float*)d_in[8];
    const float* b_up  = (const float*)d_in[9];
    const float* W_in  = (const float*)d_in[10];
    const float* b_in  = (const float*)d_in[11];
    const float* W_fw  = (const float*)d_in[12];
    const float* b_fw  = (const float*)d_in[13];
    const float* W_lin = (const float*)d_in[14];
    const float* b_lin = (const float*)d_in[15];
    float* out = (float*)d_out;

    __half* d_WtIn; cudaGetSymbolAddress((void**)&d_WtIn, g_WtIn);
    __half* d_WtFw; cudaGetSymbolAddress((void**)&d_WtFw, g_WtFw);
    float* d_WtUp; cudaGetSymbolAddress((void**)&d_WtUp, g_WtUp);

    // ---- CSR build ----
    k_hist0<<<(SCAN_L + 255) / 256, 256>>>();
    k_hist<<<(NE_UP + 255) / 256, 256>>>(eidx + NE_UP, NE_UP, 0);
    for (int il = 0; il < NLY; il++)
        k_hist<<<(NE_L + 255) / 256, 256>>>(einner + (size_t)il * 2 * NE_L + NE_L, NE_L, 1 + il);
    for (int il = 0; il < NLY; il++)
        k_hist<<<(NE_L + 255) / 256, 256>>>(efw + (size_t)il * 2 * NE_L + NE_L, NE_L, 5 + il);
    k_scan1<<<SCAN_NB, 256>>>();
    k_scan2<<<1, 1024>>>();
    k_scan3<<<SCAN_NB, 256>>>();
    k_dinv<<<(SCAN_L + 255) / 256, 256>>>();
    k_cursor<<<(SCAN_L + 255) / 256, 256>>>();
    k_fill<<<(NE_UP + 255) / 256, 256>>>(eidx, eidx + NE_UP, NE_UP, 0);
    for (int il = 0; il < NLY; il++)
        k_fill<<<(NE_L + 255) / 256, 256>>>(einner + (size_t)il * 2 * NE_L,
                                            einner + (size_t)il * 2 * NE_L + NE_L, NE_L, 1 + il);
    for (int il = 0; il < NLY; il++)
        k_fill<<<(NE_L + 255) / 256, 256>>>(efw + (size_t)il * 2 * NE_L,
                                            efw + (size_t)il * 2 * NE_L + NE_L, NE_L, 5 + il);
    k_build<<<(Nn + 255) / 256, 256>>>(layers);
    k_transpose_h<<<(FA * 256 + 255) / 256, 256>>>(W_in, d_WtIn, FA);
    k_transpose_h<<<(FA * 256 + 255) / 256, 256>>>(W_fw, d_WtFw, FA);
    k_transpose<<<(16 * 256 + 255) / 256, 256>>>(W_up, d_WtUp, 16);
    k_stat_h<<<(Nn * FS + 255) / 256, 256>>>(stat);

    const int GX = (Nn + 127) / 128;

    // ---- up conv ----
    k_up_gather<<<(Nn * 4 + 255) / 256, 256>>>(x16);
    k_mma_gemm_up<<<dim3(GX, 2), 256>>>(b_up);

    auto conv = [&](int slot, int mask, const __half* Wt, const float* bb, int to_pi) {
        k_gather<<<(Nn + 7) / 8, 256>>>(slot, mask);
        k_mma_gemm<<<dim3(GX, 2), 256>>>(Wt, bb, mask, to_pi);
    };

    for (int p = 0; p < 2; p++) {
        for (int il = 0; il < 3; il++) {
            conv(1 + il, il, d_WtIn, b_in, 0);          // inner -> rows(il)
            conv(5 + il, il + 1, d_WtFw, b_fw, 0);      // fw    -> rows(il+1)
        }
        conv(4, -1, d_WtIn, b_in, 1);                   // full -> pi
        k_copy_rows<<<(Nn + 7) / 8, 256>>>(3);
        k_relu4<<<(Nn * F / 8 + 255) / 256, 256>>>();
        for (int il = 3; il >= 0; il--) {
            if (il >= 1) k_copy_rows<<<(Nn + 7) / 8, 256>>>(il - 1);
            conv(1 + il, il, d_WtIn, b_in, 0);
        }
        k_relu4<<<(Nn * F / 8 + 255) / 256, 256>>>();
    }

    k_pool_init<<<1, 64>>>(b_lin, out);
    k_pool<<<(Nn * 32 + 255) / 256, 256>>>(batch, W_lin, out);
}

// round 14
// speedup vs baseline: 1.7848x; 1.0827x over previous
#include <cuda_runtime.h>
#include <cuda_fp16.h>
#include <cstdint>

#define Nn    100000
#define F     256
#define FS    32
#define FA    288
#define NLY   4
#define NG    50
#define NE_UP 400000
#define NE_L  300000
#define NE_TOT (NE_UP + 8 * NE_L)
#define SCAN_L (9 * Nn)
#define SCAN_BLK 1024
#define SCAN_NB ((SCAN_L + SCAN_BLK - 1) / SCAN_BLK)

// ---------------- device scratch ----------------
__device__ __half g_x[(size_t)Nn * F];
__device__ __half g_pi[(size_t)Nn * F];
__device__ __half g_agg[(size_t)Nn * FA];
__device__ __half g_stat_h[(size_t)Nn * FS];
__device__ float g_agg16[(size_t)Nn * 16];
__device__ float g_dinv[(size_t)SCAN_L];
__device__ int   g_hist[(size_t)SCAN_L];
__device__ int   g_rp[(size_t)SCAN_L + 1];
__device__ int   g_col[(size_t)NE_TOT];
__device__ float g_we[(size_t)NE_TOT];
__device__ int   g_bsum[SCAN_NB];
__device__ int   g_boff[SCAN_NB];
__device__ int   g_total;
__device__ int   g_rows[(size_t)NLY * Nn];
__device__ int   g_cnt[NLY];
__device__ __half g_WtIn[(size_t)256 * FA];
__device__ __half g_WtFw[(size_t)256 * FA];
__device__ float g_WtUp[(size_t)256 * 16];

__device__ __forceinline__ uint32_t f2tf32(float f) {
    uint32_t r; asm("cvt.rna.tf32.f32 %0, %1;" : "=r"(r) : "f"(f)); return r;
}
__device__ __forceinline__ uint4 tf4(float4 v) {
    return make_uint4(f2tf32(v.x), f2tf32(v.y), f2tf32(v.z), f2tf32(v.w));
}
__device__ __forceinline__ void mma_tf32(float* d, const uint32_t* a, const uint32_t* b) {
    asm volatile(
        "mma.sync.aligned.m16n8k8.row.col.f32.tf32.tf32.f32 "
        "{%0,%1,%2,%3}, {%4,%5,%6,%7}, {%8,%9}, {%0,%1,%2,%3};"
        : "+f"(d[0]), "+f"(d[1]), "+f"(d[2]), "+f"(d[3])
        : "r"(a[0]), "r"(a[1]), "r"(a[2]), "r"(a[3]), "r"(b[0]), "r"(b[1]));
}
__device__ __forceinline__ void mma_f16(float* d, const uint32_t* a, const uint32_t* b) {
    asm volatile(
        "mma.sync.aligned.m16n8k16.row.col.f32.f16.f16.f32 "
        "{%0,%1,%2,%3}, {%4,%5,%6,%7}, {%8,%9}, {%0,%1,%2,%3};"
        : "+f"(d[0]), "+f"(d[1]), "+f"(d[2]), "+f"(d[3])
        : "r"(a[0]), "r"(a[1]), "r"(a[2]), "r"(a[3]), "r"(b[0]), "r"(b[1]));
}
__device__ __forceinline__ float4 fmaf4(float4 a, float w, float4 v) {
    a.x = fmaf(w, v.x, a.x); a.y = fmaf(w, v.y, a.y);
    a.z = fmaf(w, v.z, a.z); a.w = fmaf(w, v.w, a.w);
    return a;
}
__device__ __forceinline__ void unpack8h(uint4 r, float* a) {
    float2 f;
    f = __half22float2(*(__half2*)&r.x); a[0] = f.x; a[1] = f.y;
    f = __half22float2(*(__half2*)&r.y); a[2] = f.x; a[3] = f.y;
    f = __half22float2(*(__half2*)&r.z); a[4] = f.x; a[5] = f.y;
    f = __half22float2(*(__half2*)&r.w); a[6] = f.x; a[7] = f.y;
}
__device__ __forceinline__ void unpack4h(uint2 r, float* a) {
    float2 f;
    f = __half22float2(*(__half2*)&r.x); a[0] = f.x; a[1] = f.y;
    f = __half22float2(*(__half2*)&r.y); a[2] = f.x; a[3] = f.y;
}
__device__ __forceinline__ uint4 pack8h(const float* a) {
    uint4 r;
    __half2 h;
    h = __floats2half2_rn(a[0], a[1]); r.x = *(uint32_t*)&h;
    h = __floats2half2_rn(a[2], a[3]); r.y = *(uint32_t*)&h;
    h = __floats2half2_rn(a[4], a[5]); r.z = *(uint32_t*)&h;
    h = __floats2half2_rn(a[6], a[7]); r.w = *(uint32_t*)&h;
    return r;
}

// ---------------- CSR build (deduped multi-set, R7-verified kernels) ----------------
__global__ void k_hist0() {
    int i = blockIdx.x * blockDim.x + threadIdx.x;
    if (i < SCAN_L) g_hist[i] = 0;
    if (i < NLY) g_cnt[i] = 0;
}
__global__ void k_hist_multi(const int* __restrict__ base, int per, int nsets, int slot0) {
    int i = blockIdx.x * blockDim.x + threadIdx.x;
    if (i >= per * nsets) return;
    int set = i / per, e = i - set * per;
    int d = base[(size_t)set * 2 * per + per + e];
    atomicAdd(&g_hist[(size_t)(slot0 + set) * Nn + d], 1);
}
__global__ void k_scan1() {
    __shared__ int ws[8];
    int t = threadIdx.x;
    int base = blockIdx.x * SCAN_BLK + t * 4;
    int v[4], s = 0;
#pragma unroll
    for (int j = 0; j < 4; j++) {
        v[j] = (base + j < SCAN_L) ? g_hist[base + j] : 0;
        s += v[j];
    }
    int lane = t & 31, w = t >> 5;
    int inc = s;
#pragma unroll
    for (int o = 1; o < 32; o <<= 1) {
        int x = __shfl_up_sync(0xffffffffu, inc, o);
        if (lane >= o) inc += x;
    }
    if (lane == 31) ws[w] = inc;
    __syncthreads();
    if (t < 8) {
        int x = ws[t];
#pragma unroll
        for (int o = 1; o < 8; o <<= 1) {
            int y = __shfl_up_sync(0xffu, x, o);
            if (t >= o) x += y;
        }
        ws[t] = x;
    }
    __syncthreads();
    int run = inc - s + (w > 0 ? ws[w - 1] : 0);
#pragma unroll
    for (int j = 0; j < 4; j++) {
        if (base + j < SCAN_L) g_rp[base + j] = run;
        run += v[j];
    }
    __syncthreads();
    if (t == 255) g_bsum[blockIdx.x] = ws[7];
}
__global__ void k_scan2() {
    __shared__ int ws[32];
    int t = threadIdx.x;
    int v = (t < SCAN_NB) ? g_bsum[t] : 0;
    int lane = t & 31, w = t >> 5;
    int inc = v;
#pragma unroll
    for (int o = 1; o < 32; o <<= 1) {
        int x = __shfl_up_sync(0xffffffffu, inc, o);
        if (lane >= o) inc += x;
    }
    if (lane == 31) ws[w] = inc;
    __syncthreads();
    if (t < 32) {
        int x = ws[t];
#pragma unroll
        for (int o = 1; o < 32; o <<= 1) {
            int y = __shfl_up_sync(0xffffffffu, x, o);
            if (t >= o) x += y;
        }
        ws[t] = x;
    }
    __syncthreads();
    int excl = inc - v + (w > 0 ? ws[w - 1] : 0);
    if (t < SCAN_NB) g_boff[t] = excl;
    if (t == SCAN_NB - 1) g_total = excl + v;
}
__global__ void k_scan3() {     // + dinv + cursor fused (R7-verified)
    int t = threadIdx.x;
    int off = g_boff[blockIdx.x];
    int base = blockIdx.x * SCAN_BLK + t * 4;
#pragma unroll
    for (int j = 0; j < 4; j++) {
        int i = base + j;
        if (i < SCAN_L) {
            int deg = g_hist[i];
            int rpv = g_rp[i] + off;
            g_rp[i] = rpv;
            g_dinv[i] = rsqrtf((float)(deg + 1));
            g_hist[i] = rpv;            // fill cursor
        }
    }
    if (blockIdx.x == 0 && t == 0) g_rp[SCAN_L] = g_total;
}
__global__ void k_fill_multi(const int* __restrict__ base, int per, int nsets, int slot0) {
    int i = blockIdx.x * blockDim.x + threadIdx.x;
    if (i >= per * nsets) return;
    int set = i / per, e = i - set * per;
    const int* eb = base + (size_t)set * 2 * per;
    int s = eb[e], d = eb[per + e];
    int slot = slot0 + set;
    int pos = atomicAdd(&g_hist[(size_t)slot * Nn + d], 1);
    g_col[pos] = s;
    g_we[pos] = g_dinv[(size_t)slot * Nn + s];
}
__global__ void k_build(const int* __restrict__ layers) {
    int n = blockIdx.x * blockDim.x + threadIdx.x;
    if (n >= Nn) return;
    int il = layers[n];
    int p = atomicAdd(&g_cnt[il], 1);
    g_rows[(size_t)il * Nn + p] = n;
}
__global__ void k_transpose_h(const float* __restrict__ W, __half* __restrict__ Wt, int K) {
    int i = blockIdx.x * blockDim.x + threadIdx.x;
    if (i >= K * 256) return;
    int k = i >> 8, n = i & 255;
    Wt[(size_t)n * K + k] = __float2half_rn(W[i]);
}
__global__ void k_transpose(const float* __restrict__ W, float* __restrict__ Wt, int K) {
    int i = blockIdx.x * blockDim.x + threadIdx.x;
    if (i >= K * 256) return;
    int k = i >> 8, n = i & 255;
    Wt[(size_t)n * K + k] = W[i];
}
__global__ void k_stat_h(const float* __restrict__ stat) {
    int i = blockIdx.x * blockDim.x + threadIdx.x;
    if (i < Nn * FS) g_stat_h[i] = __float2half_rn(stat[i]);
}

// ---------------- up conv ----------------
__global__ void k_up_gather(const float* __restrict__ x16) {
    int i = blockIdx.x * blockDim.x + threadIdx.x;
    if (i >= Nn * 4) return;
    int n = i >> 2, q = i & 3;
    float dd = g_dinv[n];
    int r0 = g_rp[n], r1 = g_rp[n + 1];
    float4 a = ((const float4*)(x16 + (size_t)n * 16))[q];
    a.x *= dd; a.y *= dd; a.z *= dd; a.w *= dd;
    for (int e = r0; e < r1; e++) {
        int s = g_col[e];
        float wgt = g_we[e];
        a = fmaf4(a, wgt, ((const float4*)(x16 + (size_t)s * 16))[q]);
    }
    a.x *= dd; a.y *= dd; a.z *= dd; a.w *= dd;
    ((float4*)(g_agg16 + (size_t)n * 16))[q] = a;
}

#define ASTRIDE 36
__global__ void __launch_bounds__(256)
k_mma_gemm_up(const float* __restrict__ bias) {
    __shared__ uint32_t As[128 * ASTRIDE];
    __shared__ uint32_t Bs[128 * ASTRIDE];
    int row0 = blockIdx.x * 128;
    int colb = blockIdx.y * 128;
    int tid = threadIdx.x, wid = tid >> 5, lane = tid & 31;
    int wm = (wid >> 2) * 64, wn = (wid & 3) * 32;
    int q = lane >> 2, t = lane & 3;

    float acc[4][4][4];
#pragma unroll
    for (int i = 0; i < 4; i++)
#pragma unroll
        for (int j = 0; j < 4; j++)
#pragma unroll
            for (int k = 0; k < 4; k++) acc[i][j][k] = 0.f;
    {
        int idx = tid;
        for (int i = 0; i < 2; i++) {
            int e = idx + i * 256;
            int m = e >> 2, k4 = e & 3;
            int g = row0 + m;
            uint4 v = make_uint4(0, 0, 0, 0);
            if (g < Nn) v = tf4(*(const float4*)(g_agg16 + (size_t)g * 16 + k4 * 4));
            *(uint4*)(&As[m * ASTRIDE + k4 * 4]) = v;
        }
        for (int i = 0; i < 2; i++) {
            int e = idx + i * 256;
            int n = e >> 2, k4 = e & 3;
            float4 f = *(const float4*)(g_WtUp + (size_t)(colb + n) * 16 + k4 * 4);
            *(uint4*)(&Bs[n * ASTRIDE + k4 * 4]) = tf4(f);
        }
    }
    __syncthreads();
#pragma unroll
    for (int ks = 0; ks < 2; ks++) {
        int kc = ks * 8;
        uint32_t af[4][4];
#pragma unroll
        for (int mt = 0; mt < 4; mt++) {
            int r = wm + mt * 16 + q;
            af[mt][0] = As[r * ASTRIDE + kc + t];
            af[mt][1] = As[(r + 8) * ASTRIDE + kc + t];
            af[mt][2] = As[r * ASTRIDE + kc + t + 4];
            af[mt][3] = As[(r + 8) * ASTRIDE + kc + t + 4];
        }
        uint32_t bf[4][2];
#pragma unroll
        for (int nt = 0; nt < 4; nt++) {
            int n = wn + nt * 8 + q;
            bf[nt][0] = Bs[n * ASTRIDE + kc + t];
            bf[nt][1] = Bs[n * ASTRIDE + kc + t + 4];
        }
#pragma unroll
        for (int mt = 0; mt < 4; mt++)
#pragma unroll
            for (int nt = 0; nt < 4; nt++)
                mma_tf32(acc[mt][nt], af[mt], bf[nt]);
    }
#pragma unroll
    for (int mt = 0; mt < 4; mt++) {
        int n0 = row0 + wm + mt * 16 + q;
        int n1 = n0 + 8;
#pragma unroll
        for (int nt = 0; nt < 4; nt++) {
            int col = colb + wn + nt * 8 + t * 2;
            float b0 = bias[col], b1 = bias[col + 1];
            if (n0 < Nn) {
                __half2 h = __floats2half2_rn(acc[mt][nt][0] + b0, acc[mt][nt][1] + b1);
                ((uint32_t*)(g_x + (size_t)n0 * F))[col >> 1] = *(uint32_t*)&h;
            }
            if (n1 < Nn) {
                __half2 h = __floats2half2_rn(acc[mt][nt][2] + b0, acc[mt][nt][3] + b1);
                ((uint32_t*)(g_x + (size_t)n1 * F))[col >> 1] = *(uint32_t*)&h;
            }
        }
    }
}

// ---------------- gather with pi-deferral ----------------
// Reads pi[s] instead of x[s] when layers[s]==pl1 || layers[s]==pl2 (pl<0 disables).
__global__ void __launch_bounds__(256)
k_gather(int slot, int mask_il, const int* __restrict__ layers, int pl1, int pl2) {
    int w = threadIdx.x >> 5, lane = threadIdx.x & 31;
    int idx = blockIdx.x * 8 + w;
    int cnt = (mask_il >= 0) ? g_cnt[mask_il] : Nn;
    if (idx >= cnt) return;
    int n = (mask_il >= 0) ? g_rows[(size_t)mask_il * Nn + idx] : idx;
    size_t sb = (size_t)slot * Nn;
    float dd = g_dinv[sb + n];
    int e = g_rp[sb + n], e1 = g_rp[sb + n + 1];
    bool defer = (pl1 >= 0) || (pl2 >= 0);

    // self row: layers[n] == mask_il (when masked)
    const __half* selfb = g_x;
    if (defer && mask_il >= 0 && (mask_il == pl1 || mask_il == pl2)) selfb = g_pi;
    float a[8];
    unpack8h(((const uint4*)(selfb + (size_t)n * F))[lane], a);
    float st[4] = {0.f, 0.f, 0.f, 0.f};
    if (lane < 8)
        unpack4h(((const uint2*)(g_stat_h + (size_t)n * FS))[lane], st);
#pragma unroll
    for (int j = 0; j < 8; j++) a[j] *= dd;
#pragma unroll
    for (int j = 0; j < 4; j++) st[j] *= dd;

    for (; e + 1 < e1; e += 2) {
        int s0 = g_col[e], s1 = g_col[e + 1];
        float w0 = g_we[e], w1 = g_we[e + 1];
        const __half* b0 = g_x;
        const __half* b1 = g_x;
        if (defer) {
            int l0 = layers[s0], l1 = layers[s1];
            if (l0 == pl1 || l0 == pl2) b0 = g_pi;
            if (l1 == pl1 || l1 == pl2) b1 = g_pi;
        }
        uint4 r0 = ((const uint4*)(b0 + (size_t)s0 * F))[lane];
        uint4 r1 = ((const uint4*)(b1 + (size_t)s1 * F))[lane];
        float x0[8], x1[8];
        unpack8h(r0, x0);
        unpack8h(r1, x1);
#pragma unroll
        for (int j = 0; j < 8; j++) {
            a[j] = fmaf(w0, x0[j], a[j]);
            a[j] = fmaf(w1, x1[j], a[j]);
        }
        if (lane < 8) {
            uint2 t0 = ((const uint2*)(g_stat_h + (size_t)s0 * FS))[lane];
            uint2 t1 = ((const uint2*)(g_stat_h + (size_t)s1 * FS))[lane];
            float y0[4], y1[4];
            unpack4h(t0, y0);
            unpack4h(t1, y1);
#pragma unroll
            for (int j = 0; j < 4; j++) {
                st[j] = fmaf(w0, y0[j], st[j]);
                st[j] = fmaf(w1, y1[j], st[j]);
            }
        }
    }
    if (e < e1) {
        int s = g_col[e];
        float wgt = g_we[e];
        const __half* bb = g_x;
        if (defer) {
            int ls = layers[s];
            if (ls == pl1 || ls == pl2) bb = g_pi;
        }
        float xs[8];
        unpack8h(((const uint4*)(bb + (size_t)s * F))[lane], xs);
#pragma unroll
        for (int j = 0; j < 8; j++) a[j] = fmaf(wgt, xs[j], a[j]);
        if (lane < 8) {
            float ys[4];
            unpack4h(((const uint2*)(g_stat_h + (size_t)s * FS))[lane], ys);
#pragma unroll
            for (int j = 0; j < 4; j++) st[j] = fmaf(wgt, ys[j], st[j]);
        }
    }
#pragma unroll
    for (int j = 0; j < 8; j++) a[j] *= dd;
#pragma unroll
    for (int j = 0; j < 4; j++) st[j] *= dd;

    __half* ag = g_agg + (size_t)n * FA;
    ((uint4*)ag)[lane] = pack8h(a);
    if (lane < 8) {
        __half2 h0 = __floats2half2_rn(st[0], st[1]);
        __half2 h1 = __floats2half2_rn(st[2], st[3]);
        ((uint2*)(ag + 256))[lane] = make_uint2(*(uint32_t*)&h0, *(uint32_t*)&h1);
    }
}

// ---------------- fp16 GEMM, double-buffered (R13) ----------------
#define BST 20
#define NCHUNK 9
__global__ void __launch_bounds__(256)
k_mma_gemm(const __half* __restrict__ Wt, const float* __restrict__ bias,
           int mask_il, int to_pi) {
    __shared__ uint32_t As[2][128 * BST];
    __shared__ uint32_t Bs[2][128 * BST];

    int cnt = (mask_il >= 0) ? g_cnt[mask_il] : Nn;
    const int* list = (mask_il >= 0) ? (g_rows + (size_t)mask_il * Nn) : nullptr;
    int row0 = blockIdx.x * 128;
    if (row0 >= cnt) return;
    int colb = blockIdx.y * 128;

    int tid = threadIdx.x, wid = tid >> 5, lane = tid & 31;
    int wm = (wid >> 2) * 64;
    int wn = (wid & 3) * 32;
    int q = lane >> 2, t = lane & 3;

    float acc[4][4][4];
#pragma unroll
    for (int i = 0; i < 4; i++)
#pragma unroll
        for (int j = 0; j < 4; j++)
#pragma unroll
            for (int k = 0; k < 4; k++) acc[i][j][k] = 0.f;

    int lm[2], lk[2];
    int amrow[2];
#pragma unroll
    for (int i = 0; i < 2; i++) {
        int idx = tid + i * 256;
        lm[i] = idx >> 2;
        lk[i] = idx & 3;
        int g = row0 + lm[i];
        amrow[i] = (g < cnt) ? (list ? list[g] : g) : (list ? list[row0] : row0);
    }

#pragma unroll
    for (int i = 0; i < 2; i++) {
        uint4 va = *(const uint4*)((const uint32_t*)(g_agg + (size_t)amrow[i] * FA) + lk[i] * 4);
        *(uint4*)(&As[0][lm[i] * BST + lk[i] * 4]) = va;
        uint4 vb = *(const uint4*)((const uint32_t*)(Wt + (size_t)(colb + lm[i]) * FA) + lk[i] * 4);
        *(uint4*)(&Bs[0][lm[i] * BST + lk[i] * 4]) = vb;
    }
    __syncthreads();

#pragma unroll
    for (int c = 0; c < NCHUNK; c++) {
        int buf = c & 1;
        uint4 va[2], vb[2];
        if (c + 1 < NCHUNK) {
            int koff = (c + 1) * 16;
#pragma unroll
            for (int i = 0; i < 2; i++) {
                va[i] = *(const uint4*)((const uint32_t*)(g_agg + (size_t)amrow[i] * FA)
                                        + koff + lk[i] * 4);
                vb[i] = *(const uint4*)((const uint32_t*)(Wt + (size_t)(colb + lm[i]) * FA)
                                        + koff + lk[i] * 4);
            }
        }
#pragma unroll
        for (int ks = 0; ks < 2; ks++) {
            int kc = ks * 8;
            uint32_t af[4][4];
#pragma unroll
            for (int mt = 0; mt < 4; mt++) {
                int r = wm + mt * 16 + q;
                af[mt][0] = As[buf][r * BST + kc + t];
                af[mt][1] = As[buf][(r + 8) * BST + kc + t];
                af[mt][2] = As[buf][r * BST + kc + t + 4];
                af[mt][3] = As[buf][(r + 8) * BST + kc + t + 4];
            }
            uint32_t bf[4][2];
#pragma unroll
            for (int nt = 0; nt < 4; nt++) {
                int n = wn + nt * 8 + q;
                bf[nt][0] = Bs[buf][n * BST + kc + t];
                bf[nt][1] = Bs[buf][n * BST + kc + t + 4];
            }
#pragma unroll
            for (int mt = 0; mt < 4; mt++)
#pragma unroll
                for (int nt = 0; nt < 4; nt++)
                    mma_f16(acc[mt][nt], af[mt], bf[nt]);
        }
        if (c + 1 < NCHUNK) {
            int nb = buf ^ 1;
#pragma unroll
            for (int i = 0; i < 2; i++) {
                *(uint4*)(&As[nb][lm[i] * BST + lk[i] * 4]) = va[i];
                *(uint4*)(&Bs[nb][lm[i] * BST + lk[i] * 4]) = vb[i];
            }
            __syncthreads();
        }
    }

    __half* outb = to_pi ? g_pi : g_x;
#pragma unroll
    for (int mt = 0; mt < 4; mt++) {
        int g0 = row0 + wm + mt * 16 + q;
        int g1 = g0 + 8;
        int n0 = (g0 < cnt) ? (list ? list[g0] : g0) : -1;
        int n1 = (g1 < cnt) ? (list ? list[g1] : g1) : -1;
#pragma unroll
        for (int nt = 0; nt < 4; nt++) {
            int col = colb + wn + nt * 8 + t * 2;
            float b0 = bias[col], b1 = bias[col + 1];
            if (n0 >= 0) {
                __half2 h = __floats2half2_rn(acc[mt][nt][0] + b0, acc[mt][nt][1] + b1);
                ((uint32_t*)(outb + (size_t)n0 * F))[col >> 1] = *(uint32_t*)&h;
            }
            if (n1 >= 0) {
                __half2 h = __floats2half2_rn(acc[mt][nt][2] + b0, acc[mt][nt][3] + b1);
                ((uint32_t*)(outb + (size_t)n1 * F))[col >> 1] = *(uint32_t*)&h;
            }
        }
    }
}

// ---------------- misc ----------------
// x = relu(layers==3 ? pi : x)   (32 uint4 per row)
__global__ void k_relu_copy3(const int* __restrict__ layers) {
    int i = blockIdx.x * blockDim.x + threadIdx.x;
    if (i >= Nn * F / 8) return;
    int n = i >> 5;
    uint4 v = (layers[n] == 3) ? ((const uint4*)g_pi)[i] : ((const uint4*)g_x)[i];
    __half2 z = __float2half2_rn(0.f);
    *(__half2*)&v.x = __hmax2(*(__half2*)&v.x, z);
    *(__half2*)&v.y = __hmax2(*(__half2*)&v.y, z);
    *(__half2*)&v.z = __hmax2(*(__half2*)&v.z, z);
    *(__half2*)&v.w = __hmax2(*(__half2*)&v.w, z);
    ((uint4*)g_x)[i] = v;
}
__global__ void k_relu4() {
    int i = blockIdx.x * blockDim.x + threadIdx.x;
    if (i >= Nn * F / 8) return;
    uint4 v = ((uint4*)g_x)[i];
    __half2 z = __float2half2_rn(0.f);
    *(__half2*)&v.x = __hmax2(*(__half2*)&v.x, z);
    *(__half2*)&v.y = __hmax2(*(__half2*)&v.y, z);
    *(__half2*)&v.z = __hmax2(*(__half2*)&v.z, z);
    *(__half2*)&v.w = __hmax2(*(__half2*)&v.w, z);
    ((uint4*)g_x)[i] = v;
}
__global__ void k_pool_init(const float* __restrict__ bl, float* __restrict__ out) {
    int g = threadIdx.x;
    if (g < NG) out[g] = bl[0];
}
__global__ void k_pool(const int* __restrict__ batch, const float* __restrict__ Wl,
                       float* __restrict__ out) {
    int w = (blockIdx.x * blockDim.x + threadIdx.x) >> 5;
    int lane = threadIdx.x & 31;
    if (w >= Nn) return;
    const uint32_t* xr = (const uint32_t*)(g_x + (size_t)w * F);
    float s = 0.f;
    for (int c = lane; c < 128; c += 32) {
        float2 f = __half22float2(*(const __half2*)&xr[c]);
        s += f.x * Wl[2 * c] + f.y * Wl[2 * c + 1];
    }
#pragma unroll
    for (int o = 16; o; o >>= 1) s += __shfl_down_sync(0xffffffffu, s, o);
    if (lane == 0) atomicAdd(&out[batch[w]], s);
}

// ---------------- orchestration ----------------
extern "C" void kernel_launch(void* const* d_in, const int* in_sizes, int n_in,
                              void* d_out, int out_size) {
    const float* x16    = (const float*)d_in[0];
    const float* stat   = (const float*)d_in[1];
    const int*   eidx   = (const int*)d_in[2];
    const int*   einner = (const int*)d_in[3];
    const int*   efw    = (const int*)d_in[4];
    const int*   layers = (const int*)d_in[6];
    const int*   batch  = (const int*)d_in[7];
    const float* W_up  = (const float*)d_in[8];
    const float* b_up  = (const float*)d_in[9];
    const float* W_in  = (const float*)d_in[10];
    const float* b_in  = (const float*)d_in[11];
    const float* W_fw  = (const float*)d_in[12];
    const float* b_fw  = (const float*)d_in[13];
    const float* W_lin = (const float*)d_in[14];
    const float* b_lin = (const float*)d_in[15];
    float* out = (float*)d_out;

    __half* d_WtIn; cudaGetSymbolAddress((void**)&d_WtIn, g_WtIn);
    __half* d_WtFw; cudaGetSymbolAddress((void**)&d_WtFw, g_WtFw);
    float* d_WtUp; cudaGetSymbolAddress((void**)&d_WtUp, g_WtUp);

    // ---- CSR build (deduped launches) ----
    k_hist0<<<(SCAN_L + 255) / 256, 256>>>();
    k_hist_multi<<<(NE_UP + 255) / 256, 256>>>(eidx, NE_UP, 1, 0);
    k_hist_multi<<<(4 * NE_L + 255) / 256, 256>>>(einner, NE_L, 4, 1);
    k_hist_multi<<<(4 * NE_L + 255) / 256, 256>>>(efw, NE_L, 4, 5);
    k_scan1<<<SCAN_NB, 256>>>();
    k_scan2<<<1, 1024>>>();
    k_scan3<<<SCAN_NB, 256>>>();
    k_fill_multi<<<(NE_UP + 255) / 256, 256>>>(eidx, NE_UP, 1, 0);
    k_fill_multi<<<(4 * NE_L + 255) / 256, 256>>>(einner, NE_L, 4, 1);
    k_fill_multi<<<(4 * NE_L + 255) / 256, 256>>>(efw, NE_L, 4, 5);
    k_build<<<(Nn + 255) / 256, 256>>>(layers);
    k_transpose_h<<<(FA * 256 + 255) / 256, 256>>>(W_in, d_WtIn, FA);
    k_transpose_h<<<(FA * 256 + 255) / 256, 256>>>(W_fw, d_WtFw, FA);
    k_transpose<<<(16 * 256 + 255) / 256, 256>>>(W_up, d_WtUp, 16);
    k_stat_h<<<(Nn * FS + 255) / 256, 256>>>(stat);

    const int GX = (Nn + 127) / 128;
    const int GG = (Nn + 7) / 8;
    const int GR = (Nn * F / 8 + 255) / 256;

    // ---- up conv ----
    k_up_gather<<<(Nn * 4 + 255) / 256, 256>>>(x16);
    k_mma_gemm_up<<<dim3(GX, 2), 256>>>(b_up);

    auto conv = [&](int slot, int mask, const __half* Wt, const float* bb,
                    int to_pi, int pl1, int pl2) {
        k_gather<<<GG, 256>>>(slot, mask, layers, pl1, pl2);
        k_mma_gemm<<<dim3(GX, 2), 256>>>(Wt, bb, mask, to_pi);
    };

    for (int p = 0; p < 2; p++) {
        // forward sweep (no deferral)
        for (int il = 0; il < 3; il++) {
            conv(1 + il, il, d_WtIn, b_in, 0, -9, -9);
            conv(5 + il, il + 1, d_WtFw, b_fw, 0, -9, -9);
        }
        conv(4, -1, d_WtIn, b_in, 1, -9, -9);           // full -> pi
        k_relu_copy3<<<GR, 256>>>(layers);              // x = relu(rows3?pi:x)
        // backward sweep with pi-deferral (no copy kernels):
        //   at step il, neighbors with layer il-1, plus layer il when il<=2, read pi
        for (int il = 3; il >= 0; il--) {
            int pl1 = il - 1;                    // -1 at il=0 never matches
            int pl2 = (il <= 2) ? il : -9;
            conv(1 + il, il, d_WtIn, b_in, 0, pl1, pl2);
        }
        k_relu4<<<GR, 256>>>();
    }

    k_pool_init<<<1, 64>>>(b_lin, out);
    k_pool<<<(Nn * 32 + 255) / 256, 256>>>(batch, W_lin, out);
}